// round 13
// baseline (speedup 1.0000x reference)
#include <cuda_runtime.h>
#include <cuda_bf16.h>
#include <math.h>
#include <stdint.h>

// ---------------- dimensions ----------------
#define B_   8
#define T_   1024
#define BT   8192           // B_*T_
#define IN_  512
#define D_   1024
#define I_   2048
#define N_   64
#define H_   16
#define P_   128
#define K_   3
#define L_   4
#define OUT_ 512
#define CB_  1024
#define CONV_ 2176          // I_ + 2*N_
#define PROJ_ 4240          // I_ + CONV_ + H_

// ---------------- device scratch (no allocation allowed) ----------------
__device__ float g_h[(size_t)BT * D_];
__device__ float g_hn[(size_t)BT * D_];
__device__ float g_proj[(size_t)BT * PROJ_];
__device__ float g_y[2][(size_t)BT * I_];   // two N-half partials

// ---------------- helpers ----------------
__device__ __forceinline__ float block_reduce_sum(float v) {
    __shared__ float red[32];
    int lane = threadIdx.x & 31, wid = threadIdx.x >> 5;
    #pragma unroll
    for (int o = 16; o; o >>= 1) v += __shfl_xor_sync(0xffffffffu, v, o);
    if (lane == 0) red[wid] = v;
    __syncthreads();
    int nw = blockDim.x >> 5;
    v = (threadIdx.x < (unsigned)nw) ? red[threadIdx.x] : 0.f;
    if (wid == 0) {
        #pragma unroll
        for (int o = 16; o; o >>= 1) v += __shfl_xor_sync(0xffffffffu, v, o);
        if (lane == 0) red[0] = v;
    }
    __syncthreads();
    return red[0];
}

__device__ __forceinline__ float siluf(float x) {
    return x / (1.f + __expf(-x));
}

// split two fp32 values into packed bf16x2 hi + bf16x2 lo (v0 in low half)
__device__ __forceinline__ void split_bf16_pair(float v0, float v1, uint32_t& hi, uint32_t& lo) {
    __nv_bfloat162 h = __floats2bfloat162_rn(v0, v1);
    float h0 = __bfloat162float(h.x);
    float h1 = __bfloat162float(h.y);
    __nv_bfloat162 l = __floats2bfloat162_rn(v0 - h0, v1 - h1);
    hi = *reinterpret_cast<uint32_t*>(&h);
    lo = *reinterpret_cast<uint32_t*>(&l);
}

__device__ __forceinline__ void mma_bf16(float* d, const uint32_t* a, const uint32_t* b) {
    asm volatile(
        "mma.sync.aligned.m16n8k16.row.col.f32.bf16.bf16.f32 "
        "{%0,%1,%2,%3}, {%4,%5,%6,%7}, {%8,%9}, {%0,%1,%2,%3};"
        : "+f"(d[0]), "+f"(d[1]), "+f"(d[2]), "+f"(d[3])
        : "r"(a[0]), "r"(a[1]), "r"(a[2]), "r"(a[3]), "r"(b[0]), "r"(b[1]));
}

// ---------------- split-bf16 (bf16x3) tensor-core GEMM: C = A @ B (+bias)(+=C)
// EXACT R7 configuration (best measured): BM=128, BN=128, BK=32, 256 threads
// = 8 warps (4x2), warp tile 32x64, double buffered, split hoisted to store.
// A: [128][ASTR2=20] u32 -> frag banks 20*gid+t4 all distinct.
// B: [16][BSTR2=136] u32 -> frag banks 8*t4+gid all distinct.
#define ASTR2 20
#define BSTR2 136
#define A_BUF (128 * ASTR2)
#define B_BUF (16 * BSTR2)
#define GEMM_SMEM ((4 * A_BUF + 4 * B_BUF) * 4)

__global__ void __launch_bounds__(256) gemm_tc(
    const float* __restrict__ A, const float* __restrict__ Bm,
    float* __restrict__ C, int M, int N, int K,
    const float* __restrict__ bias, int accum)
{
    extern __shared__ uint32_t smem[];
    uint32_t* AsH = smem;                     // [2][A_BUF]
    uint32_t* AsL = AsH + 2 * A_BUF;
    uint32_t* BsH = AsL + 2 * A_BUF;          // [2][B_BUF]
    uint32_t* BsL = BsH + 2 * B_BUF;

    const int tid = threadIdx.x;
    const int lane = tid & 31;
    const int warp = tid >> 5;
    const int warpM = warp >> 1;              // 0..3
    const int warpN = warp & 1;               // 0..1
    const int gid = lane >> 2;                // 0..7
    const int tid4 = lane & 3;                // 0..3

    const int m0 = blockIdx.y * 128;
    const int n0 = blockIdx.x * 128;

    const int a_row = tid >> 3;
    const int a_k4 = (tid & 7) * 4;
    const int b_n4 = lane * 4;

    float acc[2][8][4];
    #pragma unroll
    for (int i = 0; i < 2; i++)
        #pragma unroll
        for (int j = 0; j < 8; j++)
            #pragma unroll
            for (int c = 0; c < 4; c++) acc[i][j][c] = 0.f;

    float4 pa[4];
    float4 pb[4];
    const bool edge = (n0 + 128 > N);

    auto loadAB = [&](int kt) {
        const int kbase = kt * 32;
        #pragma unroll
        for (int i = 0; i < 4; i++)
            pa[i] = *reinterpret_cast<const float4*>(
                A + (size_t)(m0 + a_row + 32 * i) * K + kbase + a_k4);
        const int n = n0 + b_n4;
        #pragma unroll
        for (int i = 0; i < 2; i++) {
            const int kp = warp + 8 * i;
            #pragma unroll
            for (int r = 0; r < 2; r++) {
                const size_t off = (size_t)(kbase + 2 * kp + r) * N;
                float4 v;
                if (!edge) {
                    v = *reinterpret_cast<const float4*>(Bm + off + n);
                } else {
                    v.x = (n + 0 < N) ? Bm[off + n + 0] : 0.f;
                    v.y = (n + 1 < N) ? Bm[off + n + 1] : 0.f;
                    v.z = (n + 2 < N) ? Bm[off + n + 2] : 0.f;
                    v.w = (n + 3 < N) ? Bm[off + n + 3] : 0.f;
                }
                pb[2 * i + r] = v;
            }
        }
    };

    auto smemStore = [&](int buf) {
        uint32_t* ah = AsH + buf * A_BUF;
        uint32_t* al = AsL + buf * A_BUF;
        #pragma unroll
        for (int i = 0; i < 4; i++) {
            const int m = a_row + 32 * i;
            uint2 h2, l2;
            split_bf16_pair(pa[i].x, pa[i].y, h2.x, l2.x);
            split_bf16_pair(pa[i].z, pa[i].w, h2.y, l2.y);
            const int idx = m * ASTR2 + (a_k4 >> 1);
            *reinterpret_cast<uint2*>(ah + idx) = h2;
            *reinterpret_cast<uint2*>(al + idx) = l2;
        }
        uint32_t* bh = BsH + buf * B_BUF;
        uint32_t* bl = BsL + buf * B_BUF;
        #pragma unroll
        for (int i = 0; i < 2; i++) {
            const int kp = warp + 8 * i;
            const float4 r0 = pb[2 * i];
            const float4 r1 = pb[2 * i + 1];
            uint4 h4, l4;
            split_bf16_pair(r0.x, r1.x, h4.x, l4.x);
            split_bf16_pair(r0.y, r1.y, h4.y, l4.y);
            split_bf16_pair(r0.z, r1.z, h4.z, l4.z);
            split_bf16_pair(r0.w, r1.w, h4.w, l4.w);
            const int idx = kp * BSTR2 + b_n4;
            *reinterpret_cast<uint4*>(bh + idx) = h4;
            *reinterpret_cast<uint4*>(bl + idx) = l4;
        }
    };

    auto compute = [&](int buf) {
        const uint32_t* ah_s = AsH + buf * A_BUF;
        const uint32_t* al_s = AsL + buf * A_BUF;
        const uint32_t* bh_s = BsH + buf * B_BUF;
        const uint32_t* bl_s = BsL + buf * B_BUF;
        #pragma unroll
        for (int ks = 0; ks < 2; ks++) {
            const int kp0 = ks * 8;
            uint32_t ah[2][4], al[2][4], bh[8][2], bl[8][2];
            #pragma unroll
            for (int mf = 0; mf < 2; mf++) {
                const int m = warpM * 32 + mf * 16 + gid;
                const int i0 = m * ASTR2 + kp0 + tid4;
                const int i1 = (m + 8) * ASTR2 + kp0 + tid4;
                ah[mf][0] = ah_s[i0];     al[mf][0] = al_s[i0];
                ah[mf][1] = ah_s[i1];     al[mf][1] = al_s[i1];
                ah[mf][2] = ah_s[i0 + 4]; al[mf][2] = al_s[i0 + 4];
                ah[mf][3] = ah_s[i1 + 4]; al[mf][3] = al_s[i1 + 4];
            }
            #pragma unroll
            for (int nf = 0; nf < 8; nf++) {
                const int n = warpN * 64 + nf * 8 + gid;
                const int i0 = (kp0 + tid4) * BSTR2 + n;
                const int i1 = (kp0 + tid4 + 4) * BSTR2 + n;
                bh[nf][0] = bh_s[i0]; bl[nf][0] = bl_s[i0];
                bh[nf][1] = bh_s[i1]; bl[nf][1] = bl_s[i1];
            }
            #pragma unroll
            for (int mf = 0; mf < 2; mf++)
                #pragma unroll
                for (int nf = 0; nf < 8; nf++) {
                    mma_bf16(acc[mf][nf], ah[mf], bh[nf]);
                    mma_bf16(acc[mf][nf], al[mf], bh[nf]);
                    mma_bf16(acc[mf][nf], ah[mf], bl[nf]);
                }
        }
    };

    const int nk = K >> 5;
    loadAB(0);
    smemStore(0);
    __syncthreads();
    for (int kt = 0; kt < nk; kt++) {
        const int buf = kt & 1;
        if (kt + 1 < nk) loadAB(kt + 1);
        compute(buf);
        if (kt + 1 < nk) smemStore(buf ^ 1);
        __syncthreads();
    }

    // epilogue: C rows m, cols n..n+1 (float2)
    #pragma unroll
    for (int mf = 0; mf < 2; mf++) {
        #pragma unroll
        for (int nf = 0; nf < 8; nf++) {
            const int n = n0 + warpN * 64 + nf * 8 + tid4 * 2;
            if (n >= N) continue;
            float bv0 = 0.f, bv1 = 0.f;
            if (bias) { bv0 = bias[n]; bv1 = bias[n + 1]; }
            #pragma unroll
            for (int h = 0; h < 2; h++) {
                const int m = m0 + warpM * 32 + mf * 16 + gid + h * 8;
                float v0 = acc[mf][nf][2 * h]     + bv0;
                float v1 = acc[mf][nf][2 * h + 1] + bv1;
                const size_t idx = (size_t)m * N + n;
                if (accum) { v0 += C[idx]; v1 += C[idx + 1]; }
                C[idx] = v0;
                C[idx + 1] = v1;
            }
        }
    }
}

// ---------------- rmsnorm for D_=1024 rows, float4 vectorized ----------------
__global__ void __launch_bounds__(256) rmsnorm_kernel(
    const float* __restrict__ x, const float* __restrict__ w, float* __restrict__ out)
{
    int row = blockIdx.x;
    const float4* xr = reinterpret_cast<const float4*>(x + (size_t)row * D_);
    float4 v = xr[threadIdx.x];
    float ss = v.x * v.x + v.y * v.y + v.z * v.z + v.w * v.w;
    float tot = block_reduce_sum(ss);
    float r = rsqrtf(tot * (1.f / (float)D_) + 1e-6f);
    float4 wv = reinterpret_cast<const float4*>(w)[threadIdx.x];
    float4 o;
    o.x = v.x * r * wv.x; o.y = v.y * r * wv.y;
    o.z = v.z * r * wv.z; o.w = v.w * r * wv.w;
    reinterpret_cast<float4*>(out + (size_t)row * D_)[threadIdx.x] = o;
}

// ---- FUSED conv(K=3,causal)+silu + dt softplus + sequential SSM scan --------
// One CTA per (b,h,n-half), 128 threads, unroll x2 over t.
// Conv is computed inline: each thread keeps the raw proj values of its channel
// for t-1 and t-2 in registers (zero-init == causal zero padding).
// Threads 0..31: B channels, 32..63: C channels (conv'd into smem).
// Threads 64/65: dt softplus for t / t+1 (broadcast via smem).
// All threads: own x channel conv (register-resident).
__global__ void __launch_bounds__(128) scan_kernel(
    const float* __restrict__ proj,   // [BT, PROJ_]
    const float* __restrict__ cw,     // [3, CONV_] conv weights (tap0=t-2,...)
    const float* __restrict__ cb,     // [CONV_]
    const float* __restrict__ dt_bias,// [H_]
    const float* __restrict__ A_log,  // [H_]
    const float* __restrict__ Dv,     // [H_]
    float* __restrict__ y)            // [2][BT, I_] partials
{
    const int half = blockIdx.x >> 7;         // 0/1 -> n in [0,32) or [32,64)
    const int bh = blockIdx.x & 127;
    const int b = bh >> 4;
    const int h = bh & 15;
    const int p = threadIdx.x;
    const int n_off = half * 32;

    __shared__ float sB[2][32], sC[2][32], sDT[2];

    const float a = -__expf(A_log[h]);
    const float dcoef = (half == 0) ? Dv[h] : 0.f;
    const float dtb_h = dt_bias[h];

    // x channel (conv channel index in [0, I_))
    const int xch = h * P_ + p;
    const float xw0 = cw[xch], xw1 = cw[CONV_ + xch], xw2 = cw[2 * CONV_ + xch];
    const float xbias = cb[xch];
    const int xcol = I_ + xch;                // proj column

    // B/C channel for threads p < 64 (conv channel in [I_, I_+2N))
    float bw0 = 0.f, bw1 = 0.f, bw2 = 0.f, bcbias = 0.f;
    int bccol = xcol;                         // safe dummy for p >= 64
    if (p < 64) {
        const int bcch = I_ + ((p < 32) ? (n_off + p) : (N_ + n_off + (p - 32)));
        bw0 = cw[bcch]; bw1 = cw[CONV_ + bcch]; bw2 = cw[2 * CONV_ + bcch];
        bcbias = cb[bcch];
        bccol = I_ + bcch;
    }
    const int dtcol = I_ + CONV_ + h;

    float hx1 = 0.f, hx2 = 0.f;               // raw x history (t-1, t-2)
    float hb1 = 0.f, hb2 = 0.f;               // raw B/C history

    float s[32];
    #pragma unroll
    for (int n = 0; n < 32; n++) s[n] = 0.f;

    const float* prow = proj + (size_t)b * T_ * PROJ_;
    float* yb = y + (size_t)half * BT * I_ + (size_t)b * T_ * I_ + h * P_ + p;

    for (int t = 0; t < T_; t += 2) {
        const float* r0 = prow + (size_t)t * PROJ_;
        const float* r1 = r0 + PROJ_;
        // raw loads
        const float xr0 = r0[xcol];
        const float xr1 = r1[xcol];
        float bc0 = 0.f, bc1 = 0.f;
        if (p < 64) { bc0 = r0[bccol]; bc1 = r1[bccol]; }
        if (p == 64) {
            float v = r0[dtcol] + dtb_h;
            sDT[0] = (v > 20.f) ? v : log1pf(__expf(v));
        } else if (p == 65) {
            float v = r1[dtcol] + dtb_h;
            sDT[1] = (v > 20.f) ? v : log1pf(__expf(v));
        }
        // inline conv + silu (history zero-init == causal padding)
        const float x0 = siluf(xbias + xr0 * xw2 + hx1 * xw1 + hx2 * xw0);
        const float x1 = siluf(xbias + xr1 * xw2 + xr0 * xw1 + hx1 * xw0);
        hx2 = xr0; hx1 = xr1;
        if (p < 32) {
            sB[0][p] = siluf(bcbias + bc0 * bw2 + hb1 * bw1 + hb2 * bw0);
            sB[1][p] = siluf(bcbias + bc1 * bw2 + bc0 * bw1 + hb1 * bw0);
        } else if (p < 64) {
            sC[0][p - 32] = siluf(bcbias + bc0 * bw2 + hb1 * bw1 + hb2 * bw0);
            sC[1][p - 32] = siluf(bcbias + bc1 * bw2 + bc0 * bw1 + hb1 * bw0);
        }
        hb2 = bc0; hb1 = bc1;
        __syncthreads();
        const float dt0 = sDT[0];
        const float dt1 = sDT[1];
        const float dA0 = __expf(dt0 * a);
        const float dA1 = __expf(dt1 * a);
        const float k0 = dt0 * x0;
        const float k1 = dt1 * x1;
        float y0a = 0.f, y0b = 0.f, y1a = 0.f, y1b = 0.f;
        #pragma unroll
        for (int n = 0; n < 32; n += 2) {
            s[n]     = s[n]     * dA0 + k0 * sB[0][n];     y0a += s[n]     * sC[0][n];
            s[n + 1] = s[n + 1] * dA0 + k0 * sB[0][n + 1]; y0b += s[n + 1] * sC[0][n + 1];
            s[n]     = s[n]     * dA1 + k1 * sB[1][n];     y1a += s[n]     * sC[1][n];
            s[n + 1] = s[n + 1] * dA1 + k1 * sB[1][n + 1]; y1b += s[n + 1] * sC[1][n + 1];
        }
        yb[(size_t)t * I_]       = y0a + y0b + dcoef * x0;
        yb[(size_t)(t + 1) * I_] = y1a + y1b + dcoef * x1;
        __syncthreads();
    }
}

// ------- gated rmsnorm: y = rmsnorm((y0+y1) * silu(gate)) * w, float4 ---------
__global__ void __launch_bounds__(256) grms_kernel(
    float* __restrict__ yout, const float* __restrict__ y0p, const float* __restrict__ y1p,
    const float* __restrict__ proj, const float* __restrict__ w)
{
    int row = blockIdx.x;
    const float4* y0r = reinterpret_cast<const float4*>(y0p + (size_t)row * I_);
    const float4* y1r = reinterpret_cast<const float4*>(y1p + (size_t)row * I_);
    const float4* gr = reinterpret_cast<const float4*>(proj + (size_t)row * PROJ_);
    float4 v[2];
    float ss = 0.f;
    #pragma unroll
    for (int k = 0; k < 2; k++) {
        int i = threadIdx.x + k * 256;
        float4 a = y0r[i], b = y1r[i], g = gr[i];
        v[k].x = (a.x + b.x) * siluf(g.x);
        v[k].y = (a.y + b.y) * siluf(g.y);
        v[k].z = (a.z + b.z) * siluf(g.z);
        v[k].w = (a.w + b.w) * siluf(g.w);
        ss += v[k].x * v[k].x + v[k].y * v[k].y + v[k].z * v[k].z + v[k].w * v[k].w;
    }
    float tot = block_reduce_sum(ss);
    float r = rsqrtf(tot * (1.f / (float)I_) + 1e-6f);
    #pragma unroll
    for (int k = 0; k < 2; k++) {
        int i = threadIdx.x + k * 256;
        float4 wv = reinterpret_cast<const float4*>(w)[i];
        float4 o;
        o.x = v[k].x * r * wv.x; o.y = v[k].y * r * wv.y;
        o.z = v[k].z * r * wv.z; o.w = v[k].w * r * wv.w;
        reinterpret_cast<float4*>(yout + (size_t)row * I_)[i] = o;
    }
}

// ---------------- host launcher ----------------
extern "C" void kernel_launch(void* const* d_in, const int* in_sizes, int n_in,
                              void* d_out, int out_size)
{
    const float* x        = (const float*)d_in[0];
    const float* in_w     = (const float*)d_in[1];
    const float* in_b     = (const float*)d_in[2];
    const float* norm_w   = (const float*)d_in[3];
    const float* mix_in_w = (const float*)d_in[4];
    const float* conv_w   = (const float*)d_in[5];
    const float* conv_b   = (const float*)d_in[6];
    const float* dt_bias  = (const float*)d_in[7];
    const float* A_log    = (const float*)d_in[8];
    const float* Dvec     = (const float*)d_in[9];
    const float* gnorm_w  = (const float*)d_in[10];
    const float* mix_out_w= (const float*)d_in[11];
    const float* out_w    = (const float*)d_in[12];
    const float* out_b    = (const float*)d_in[13];
    const float* code_w   = (const float*)d_in[14];
    const float* code_b   = (const float*)d_in[15];
    float* out = (float*)d_out;

    float *h, *hn, *proj, *yb;
    cudaGetSymbolAddress((void**)&h,    g_h);
    cudaGetSymbolAddress((void**)&hn,   g_hn);
    cudaGetSymbolAddress((void**)&proj, g_proj);
    cudaGetSymbolAddress((void**)&yb,   g_y);
    float* yb0 = yb;
    float* yb1 = yb + (size_t)BT * I_;

    cudaFuncSetAttribute(gemm_tc, cudaFuncAttributeMaxDynamicSharedMemorySize, GEMM_SMEM);

    // h = x @ in_w + in_b
    gemm_tc<<<dim3(D_ / 128, BT / 128), 256, GEMM_SMEM>>>(x, in_w, h, BT, D_, IN_, in_b, 0);

    for (int l = 0; l < L_; l++) {
        rmsnorm_kernel<<<BT, 256>>>(h, norm_w + l * D_, hn);
        gemm_tc<<<dim3((PROJ_ + 127) / 128, BT / 128), 256, GEMM_SMEM>>>(
            hn, mix_in_w + (size_t)l * D_ * PROJ_, proj, BT, PROJ_, D_, nullptr, 0);
        scan_kernel<<<2 * B_ * H_, 128>>>(
            proj, conv_w + (size_t)l * K_ * CONV_, conv_b + (size_t)l * CONV_,
            dt_bias + l * H_, A_log + l * H_, Dvec + l * H_, yb);
        grms_kernel<<<BT, 256>>>(yb0, yb0, yb1, proj, gnorm_w + (size_t)l * I_);
        gemm_tc<<<dim3(D_ / 128, BT / 128), 256, GEMM_SMEM>>>(
            yb0, mix_out_w + (size_t)l * I_ * D_, h, BT, D_, I_, nullptr, 1);
    }

    // heads
    gemm_tc<<<dim3(OUT_ / 128, BT / 128), 256, GEMM_SMEM>>>(h, out_w, out, BT, OUT_, D_, out_b, 0);
    gemm_tc<<<dim3(CB_ / 128, BT / 128), 256, GEMM_SMEM>>>(
        h, code_w, out + (size_t)BT * OUT_, BT, CB_, D_, code_b, 0);
}

// round 14
// speedup vs baseline: 1.0818x; 1.0818x over previous
#include <cuda_runtime.h>
#include <cuda_bf16.h>
#include <math.h>
#include <stdint.h>

// ---------------- dimensions ----------------
#define B_   8
#define T_   1024
#define BT   8192           // B_*T_
#define IN_  512
#define D_   1024
#define I_   2048
#define N_   64
#define H_   16
#define P_   128
#define K_   3
#define L_   4
#define OUT_ 512
#define CB_  1024
#define CONV_ 2176          // I_ + 2*N_
#define PROJ_ 4240          // I_ + CONV_ + H_
#define CC   8              // scan chunks
#define TC   128            // T_/CC
#define CH_STRIDE 4096      // P_*32 floats per state slot

// ---------------- device scratch (no allocation allowed) ----------------
__device__ float g_h[(size_t)BT * D_];
__device__ float g_hn[(size_t)BT * D_];
__device__ float g_proj[(size_t)BT * PROJ_];
__device__ float g_y[2][(size_t)BT * I_];   // two N-half partials
__device__ float g_state[(size_t)2 * B_ * H_ * CC * CH_STRIDE];  // chunk states
__device__ float g_dts[B_ * H_ * CC];       // per-chunk dt sums

// ---------------- helpers ----------------
__device__ __forceinline__ float block_reduce_sum(float v) {
    __shared__ float red[32];
    int lane = threadIdx.x & 31, wid = threadIdx.x >> 5;
    #pragma unroll
    for (int o = 16; o; o >>= 1) v += __shfl_xor_sync(0xffffffffu, v, o);
    if (lane == 0) red[wid] = v;
    __syncthreads();
    int nw = blockDim.x >> 5;
    v = (threadIdx.x < (unsigned)nw) ? red[threadIdx.x] : 0.f;
    if (wid == 0) {
        #pragma unroll
        for (int o = 16; o; o >>= 1) v += __shfl_xor_sync(0xffffffffu, v, o);
        if (lane == 0) red[0] = v;
    }
    __syncthreads();
    return red[0];
}

__device__ __forceinline__ float siluf(float x) {
    return x / (1.f + __expf(-x));
}

// split two fp32 values into packed bf16x2 hi + bf16x2 lo (v0 in low half)
__device__ __forceinline__ void split_bf16_pair(float v0, float v1, uint32_t& hi, uint32_t& lo) {
    __nv_bfloat162 h = __floats2bfloat162_rn(v0, v1);
    float h0 = __bfloat162float(h.x);
    float h1 = __bfloat162float(h.y);
    __nv_bfloat162 l = __floats2bfloat162_rn(v0 - h0, v1 - h1);
    hi = *reinterpret_cast<uint32_t*>(&h);
    lo = *reinterpret_cast<uint32_t*>(&l);
}

__device__ __forceinline__ void mma_bf16(float* d, const uint32_t* a, const uint32_t* b) {
    asm volatile(
        "mma.sync.aligned.m16n8k16.row.col.f32.bf16.bf16.f32 "
        "{%0,%1,%2,%3}, {%4,%5,%6,%7}, {%8,%9}, {%0,%1,%2,%3};"
        : "+f"(d[0]), "+f"(d[1]), "+f"(d[2]), "+f"(d[3])
        : "r"(a[0]), "r"(a[1]), "r"(a[2]), "r"(a[3]), "r"(b[0]), "r"(b[1]));
}

// ---------------- split-bf16 (bf16x3) tensor-core GEMM (R7 config) ----------
#define ASTR2 20
#define BSTR2 136
#define A_BUF (128 * ASTR2)
#define B_BUF (16 * BSTR2)
#define GEMM_SMEM ((4 * A_BUF + 4 * B_BUF) * 4)

__global__ void __launch_bounds__(256) gemm_tc(
    const float* __restrict__ A, const float* __restrict__ Bm,
    float* __restrict__ C, int M, int N, int K,
    const float* __restrict__ bias, int accum)
{
    extern __shared__ uint32_t smem[];
    uint32_t* AsH = smem;
    uint32_t* AsL = AsH + 2 * A_BUF;
    uint32_t* BsH = AsL + 2 * A_BUF;
    uint32_t* BsL = BsH + 2 * B_BUF;

    const int tid = threadIdx.x;
    const int lane = tid & 31;
    const int warp = tid >> 5;
    const int warpM = warp >> 1;
    const int warpN = warp & 1;
    const int gid = lane >> 2;
    const int tid4 = lane & 3;

    const int m0 = blockIdx.y * 128;
    const int n0 = blockIdx.x * 128;

    const int a_row = tid >> 3;
    const int a_k4 = (tid & 7) * 4;
    const int b_n4 = lane * 4;

    float acc[2][8][4];
    #pragma unroll
    for (int i = 0; i < 2; i++)
        #pragma unroll
        for (int j = 0; j < 8; j++)
            #pragma unroll
            for (int c = 0; c < 4; c++) acc[i][j][c] = 0.f;

    float4 pa[4];
    float4 pb[4];
    const bool edge = (n0 + 128 > N);

    auto loadAB = [&](int kt) {
        const int kbase = kt * 32;
        #pragma unroll
        for (int i = 0; i < 4; i++)
            pa[i] = *reinterpret_cast<const float4*>(
                A + (size_t)(m0 + a_row + 32 * i) * K + kbase + a_k4);
        const int n = n0 + b_n4;
        #pragma unroll
        for (int i = 0; i < 2; i++) {
            const int kp = warp + 8 * i;
            #pragma unroll
            for (int r = 0; r < 2; r++) {
                const size_t off = (size_t)(kbase + 2 * kp + r) * N;
                float4 v;
                if (!edge) {
                    v = *reinterpret_cast<const float4*>(Bm + off + n);
                } else {
                    v.x = (n + 0 < N) ? Bm[off + n + 0] : 0.f;
                    v.y = (n + 1 < N) ? Bm[off + n + 1] : 0.f;
                    v.z = (n + 2 < N) ? Bm[off + n + 2] : 0.f;
                    v.w = (n + 3 < N) ? Bm[off + n + 3] : 0.f;
                }
                pb[2 * i + r] = v;
            }
        }
    };

    auto smemStore = [&](int buf) {
        uint32_t* ah = AsH + buf * A_BUF;
        uint32_t* al = AsL + buf * A_BUF;
        #pragma unroll
        for (int i = 0; i < 4; i++) {
            const int m = a_row + 32 * i;
            uint2 h2, l2;
            split_bf16_pair(pa[i].x, pa[i].y, h2.x, l2.x);
            split_bf16_pair(pa[i].z, pa[i].w, h2.y, l2.y);
            const int idx = m * ASTR2 + (a_k4 >> 1);
            *reinterpret_cast<uint2*>(ah + idx) = h2;
            *reinterpret_cast<uint2*>(al + idx) = l2;
        }
        uint32_t* bh = BsH + buf * B_BUF;
        uint32_t* bl = BsL + buf * B_BUF;
        #pragma unroll
        for (int i = 0; i < 2; i++) {
            const int kp = warp + 8 * i;
            const float4 r0 = pb[2 * i];
            const float4 r1 = pb[2 * i + 1];
            uint4 h4, l4;
            split_bf16_pair(r0.x, r1.x, h4.x, l4.x);
            split_bf16_pair(r0.y, r1.y, h4.y, l4.y);
            split_bf16_pair(r0.z, r1.z, h4.z, l4.z);
            split_bf16_pair(r0.w, r1.w, h4.w, l4.w);
            const int idx = kp * BSTR2 + b_n4;
            *reinterpret_cast<uint4*>(bh + idx) = h4;
            *reinterpret_cast<uint4*>(bl + idx) = l4;
        }
    };

    auto compute = [&](int buf) {
        const uint32_t* ah_s = AsH + buf * A_BUF;
        const uint32_t* al_s = AsL + buf * A_BUF;
        const uint32_t* bh_s = BsH + buf * B_BUF;
        const uint32_t* bl_s = BsL + buf * B_BUF;
        #pragma unroll
        for (int ks = 0; ks < 2; ks++) {
            const int kp0 = ks * 8;
            uint32_t ah[2][4], al[2][4], bh[8][2], bl[8][2];
            #pragma unroll
            for (int mf = 0; mf < 2; mf++) {
                const int m = warpM * 32 + mf * 16 + gid;
                const int i0 = m * ASTR2 + kp0 + tid4;
                const int i1 = (m + 8) * ASTR2 + kp0 + tid4;
                ah[mf][0] = ah_s[i0];     al[mf][0] = al_s[i0];
                ah[mf][1] = ah_s[i1];     al[mf][1] = al_s[i1];
                ah[mf][2] = ah_s[i0 + 4]; al[mf][2] = al_s[i0 + 4];
                ah[mf][3] = ah_s[i1 + 4]; al[mf][3] = al_s[i1 + 4];
            }
            #pragma unroll
            for (int nf = 0; nf < 8; nf++) {
                const int n = warpN * 64 + nf * 8 + gid;
                const int i0 = (kp0 + tid4) * BSTR2 + n;
                const int i1 = (kp0 + tid4 + 4) * BSTR2 + n;
                bh[nf][0] = bh_s[i0]; bl[nf][0] = bl_s[i0];
                bh[nf][1] = bh_s[i1]; bl[nf][1] = bl_s[i1];
            }
            #pragma unroll
            for (int mf = 0; mf < 2; mf++)
                #pragma unroll
                for (int nf = 0; nf < 8; nf++) {
                    mma_bf16(acc[mf][nf], ah[mf], bh[nf]);
                    mma_bf16(acc[mf][nf], al[mf], bh[nf]);
                    mma_bf16(acc[mf][nf], ah[mf], bl[nf]);
                }
        }
    };

    const int nk = K >> 5;
    loadAB(0);
    smemStore(0);
    __syncthreads();
    for (int kt = 0; kt < nk; kt++) {
        const int buf = kt & 1;
        if (kt + 1 < nk) loadAB(kt + 1);
        compute(buf);
        if (kt + 1 < nk) smemStore(buf ^ 1);
        __syncthreads();
    }

    #pragma unroll
    for (int mf = 0; mf < 2; mf++) {
        #pragma unroll
        for (int nf = 0; nf < 8; nf++) {
            const int n = n0 + warpN * 64 + nf * 8 + tid4 * 2;
            if (n >= N) continue;
            float bv0 = 0.f, bv1 = 0.f;
            if (bias) { bv0 = bias[n]; bv1 = bias[n + 1]; }
            #pragma unroll
            for (int h = 0; h < 2; h++) {
                const int m = m0 + warpM * 32 + mf * 16 + gid + h * 8;
                float v0 = acc[mf][nf][2 * h]     + bv0;
                float v1 = acc[mf][nf][2 * h + 1] + bv1;
                const size_t idx = (size_t)m * N + n;
                if (accum) { v0 += C[idx]; v1 += C[idx + 1]; }
                C[idx] = v0;
                C[idx + 1] = v1;
            }
        }
    }
}

// ---------------- rmsnorm for D_=1024 rows, float4 vectorized ----------------
__global__ void __launch_bounds__(256) rmsnorm_kernel(
    const float* __restrict__ x, const float* __restrict__ w, float* __restrict__ out)
{
    int row = blockIdx.x;
    const float4* xr = reinterpret_cast<const float4*>(x + (size_t)row * D_);
    float4 v = xr[threadIdx.x];
    float ss = v.x * v.x + v.y * v.y + v.z * v.z + v.w * v.w;
    float tot = block_reduce_sum(ss);
    float r = rsqrtf(tot * (1.f / (float)D_) + 1e-6f);
    float4 wv = reinterpret_cast<const float4*>(w)[threadIdx.x];
    float4 o;
    o.x = v.x * r * wv.x; o.y = v.y * r * wv.y;
    o.z = v.z * r * wv.z; o.w = v.w * r * wv.w;
    reinterpret_cast<float4*>(out + (size_t)row * D_)[threadIdx.x] = o;
}

// ======================= chunk-parallel SSM scan ============================
// Phase 1: per (half, b, h, chunk) CTA, scan TC steps from s=0, store final
// local state + chunk dt-sum. Conv done inline (raw lookback across boundary).
__global__ void __launch_bounds__(128) scan_p1(
    const float* __restrict__ proj, const float* __restrict__ cw,
    const float* __restrict__ cb, const float* __restrict__ dt_bias,
    const float* __restrict__ A_log)
{
    const int bi = blockIdx.x;
    const int half = bi >> 10;
    const int c = (bi >> 7) & 7;
    const int b = (bi >> 4) & 7;
    const int h = bi & 15;
    const int p = threadIdx.x;
    const int n_off = half * 32;
    const int t0 = c * TC;

    __shared__ float sB[2][32], sDT[2];

    const float a = -__expf(A_log[h]);
    const float dtb_h = dt_bias[h];

    const int xch = h * P_ + p;
    const float xw0 = cw[xch], xw1 = cw[CONV_ + xch], xw2 = cw[2 * CONV_ + xch];
    const float xbias = cb[xch];
    const int xcol = I_ + xch;

    float bw0 = 0.f, bw1 = 0.f, bw2 = 0.f, bcbias = 0.f;
    int bccol = xcol;
    if (p < 32) {
        const int bcch = I_ + n_off + p;
        bw0 = cw[bcch]; bw1 = cw[CONV_ + bcch]; bw2 = cw[2 * CONV_ + bcch];
        bcbias = cb[bcch];
        bccol = I_ + bcch;
    }
    const int dtcol = I_ + CONV_ + h;

    const float* prow = proj + (size_t)b * T_ * PROJ_;

    float hx1 = 0.f, hx2 = 0.f, hb1 = 0.f, hb2 = 0.f;
    if (c > 0) {
        hx1 = prow[(size_t)(t0 - 1) * PROJ_ + xcol];
        hx2 = prow[(size_t)(t0 - 2) * PROJ_ + xcol];
        if (p < 32) {
            hb1 = prow[(size_t)(t0 - 1) * PROJ_ + bccol];
            hb2 = prow[(size_t)(t0 - 2) * PROJ_ + bccol];
        }
    }

    float s[32];
    #pragma unroll
    for (int n = 0; n < 32; n++) s[n] = 0.f;
    float dtsum = 0.f;

    for (int t = t0; t < t0 + TC; t += 2) {
        const float* r0 = prow + (size_t)t * PROJ_;
        const float* r1 = r0 + PROJ_;
        const float xr0 = r0[xcol];
        const float xr1 = r1[xcol];
        float bc0 = 0.f, bc1 = 0.f;
        if (p < 32) { bc0 = r0[bccol]; bc1 = r1[bccol]; }
        if (p == 64) {
            float v = r0[dtcol] + dtb_h;
            sDT[0] = (v > 20.f) ? v : log1pf(__expf(v));
        } else if (p == 65) {
            float v = r1[dtcol] + dtb_h;
            sDT[1] = (v > 20.f) ? v : log1pf(__expf(v));
        }
        const float x0 = siluf(xbias + xr0 * xw2 + hx1 * xw1 + hx2 * xw0);
        const float x1 = siluf(xbias + xr1 * xw2 + xr0 * xw1 + hx1 * xw0);
        hx2 = xr0; hx1 = xr1;
        if (p < 32) {
            sB[0][p] = siluf(bcbias + bc0 * bw2 + hb1 * bw1 + hb2 * bw0);
            sB[1][p] = siluf(bcbias + bc1 * bw2 + bc0 * bw1 + hb1 * bw0);
        }
        hb2 = bc0; hb1 = bc1;
        __syncthreads();
        const float dt0 = sDT[0];
        const float dt1 = sDT[1];
        dtsum += dt0 + dt1;
        const float dA0 = __expf(dt0 * a);
        const float dA1 = __expf(dt1 * a);
        const float k0 = dt0 * x0;
        const float k1 = dt1 * x1;
        #pragma unroll
        for (int n = 0; n < 32; n++) {
            s[n] = s[n] * dA0 + k0 * sB[0][n];
            s[n] = s[n] * dA1 + k1 * sB[1][n];
        }
        __syncthreads();
    }

    const size_t sbase = ((((size_t)half * B_ + b) * H_ + h) * CC + c) * CH_STRIDE;
    #pragma unroll
    for (int n = 0; n < 32; n++)
        g_state[sbase + n * 128 + p] = s[n];
    if (half == 0 && p == 64)
        g_dts[(b * H_ + h) * CC + c] = dtsum;
}

// Phase 2: convert local final states -> true chunk-initial states (in place).
__global__ void __launch_bounds__(128) scan_p2(const float* __restrict__ A_log)
{
    const int bi = blockIdx.x;               // [0, 256)
    const int half = bi >> 7;
    const int b = (bi >> 4) & 7;
    const int h = bi & 15;
    const int p = threadIdx.x;
    const float a = -__expf(A_log[h]);

    float s[32];
    #pragma unroll
    for (int n = 0; n < 32; n++) s[n] = 0.f;

    const size_t base0 = (((size_t)half * B_ + b) * H_ + h) * CC * CH_STRIDE;
    for (int c = 0; c < CC; c++) {
        const float D = __expf(a * g_dts[(b * H_ + h) * CC + c]);
        const size_t sb = base0 + (size_t)c * CH_STRIDE;
        #pragma unroll
        for (int n = 0; n < 32; n++) {
            const size_t idx = sb + n * 128 + p;
            const float local = g_state[idx];
            g_state[idx] = s[n];                 // now: init state of chunk c
            s[n] = s[n] * D + local;             // init state of chunk c+1
        }
    }
}

// Phase 3: rescan each chunk from its true initial state, emit y.
__global__ void __launch_bounds__(128) scan_p3(
    const float* __restrict__ proj, const float* __restrict__ cw,
    const float* __restrict__ cb, const float* __restrict__ dt_bias,
    const float* __restrict__ A_log, const float* __restrict__ Dv,
    float* __restrict__ y)
{
    const int bi = blockIdx.x;
    const int half = bi >> 10;
    const int c = (bi >> 7) & 7;
    const int b = (bi >> 4) & 7;
    const int h = bi & 15;
    const int p = threadIdx.x;
    const int n_off = half * 32;
    const int t0 = c * TC;

    __shared__ float sB[2][32], sC[2][32], sDT[2];

    const float a = -__expf(A_log[h]);
    const float dcoef = (half == 0) ? Dv[h] : 0.f;
    const float dtb_h = dt_bias[h];

    const int xch = h * P_ + p;
    const float xw0 = cw[xch], xw1 = cw[CONV_ + xch], xw2 = cw[2 * CONV_ + xch];
    const float xbias = cb[xch];
    const int xcol = I_ + xch;

    float bw0 = 0.f, bw1 = 0.f, bw2 = 0.f, bcbias = 0.f;
    int bccol = xcol;
    if (p < 64) {
        const int bcch = I_ + ((p < 32) ? (n_off + p) : (N_ + n_off + (p - 32)));
        bw0 = cw[bcch]; bw1 = cw[CONV_ + bcch]; bw2 = cw[2 * CONV_ + bcch];
        bcbias = cb[bcch];
        bccol = I_ + bcch;
    }
    const int dtcol = I_ + CONV_ + h;

    const float* prow = proj + (size_t)b * T_ * PROJ_;

    float hx1 = 0.f, hx2 = 0.f, hb1 = 0.f, hb2 = 0.f;
    if (c > 0) {
        hx1 = prow[(size_t)(t0 - 1) * PROJ_ + xcol];
        hx2 = prow[(size_t)(t0 - 2) * PROJ_ + xcol];
        if (p < 64) {
            hb1 = prow[(size_t)(t0 - 1) * PROJ_ + bccol];
            hb2 = prow[(size_t)(t0 - 2) * PROJ_ + bccol];
        }
    }

    float s[32];
    const size_t sbase = ((((size_t)half * B_ + b) * H_ + h) * CC + c) * CH_STRIDE;
    #pragma unroll
    for (int n = 0; n < 32; n++)
        s[n] = g_state[sbase + n * 128 + p];

    float* yb = y + (size_t)half * BT * I_ + (size_t)b * T_ * I_ + h * P_ + p;

    for (int t = t0; t < t0 + TC; t += 2) {
        const float* r0 = prow + (size_t)t * PROJ_;
        const float* r1 = r0 + PROJ_;
        const float xr0 = r0[xcol];
        const float xr1 = r1[xcol];
        float bc0 = 0.f, bc1 = 0.f;
        if (p < 64) { bc0 = r0[bccol]; bc1 = r1[bccol]; }
        if (p == 64) {
            float v = r0[dtcol] + dtb_h;
            sDT[0] = (v > 20.f) ? v : log1pf(__expf(v));
        } else if (p == 65) {
            float v = r1[dtcol] + dtb_h;
            sDT[1] = (v > 20.f) ? v : log1pf(__expf(v));
        }
        const float x0 = siluf(xbias + xr0 * xw2 + hx1 * xw1 + hx2 * xw0);
        const float x1 = siluf(xbias + xr1 * xw2 + xr0 * xw1 + hx1 * xw0);
        hx2 = xr0; hx1 = xr1;
        if (p < 32) {
            sB[0][p] = siluf(bcbias + bc0 * bw2 + hb1 * bw1 + hb2 * bw0);
            sB[1][p] = siluf(bcbias + bc1 * bw2 + bc0 * bw1 + hb1 * bw0);
        } else if (p < 64) {
            sC[0][p - 32] = siluf(bcbias + bc0 * bw2 + hb1 * bw1 + hb2 * bw0);
            sC[1][p - 32] = siluf(bcbias + bc1 * bw2 + bc0 * bw1 + hb1 * bw0);
        }
        hb2 = bc0; hb1 = bc1;
        __syncthreads();
        const float dt0 = sDT[0];
        const float dt1 = sDT[1];
        const float dA0 = __expf(dt0 * a);
        const float dA1 = __expf(dt1 * a);
        const float k0 = dt0 * x0;
        const float k1 = dt1 * x1;
        float y0a = 0.f, y0b = 0.f, y1a = 0.f, y1b = 0.f;
        #pragma unroll
        for (int n = 0; n < 32; n += 2) {
            s[n]     = s[n]     * dA0 + k0 * sB[0][n];     y0a += s[n]     * sC[0][n];
            s[n + 1] = s[n + 1] * dA0 + k0 * sB[0][n + 1]; y0b += s[n + 1] * sC[0][n + 1];
            s[n]     = s[n]     * dA1 + k1 * sB[1][n];     y1a += s[n]     * sC[1][n];
            s[n + 1] = s[n + 1] * dA1 + k1 * sB[1][n + 1]; y1b += s[n + 1] * sC[1][n + 1];
        }
        yb[(size_t)t * I_]       = y0a + y0b + dcoef * x0;
        yb[(size_t)(t + 1) * I_] = y1a + y1b + dcoef * x1;
        __syncthreads();
    }
}

// ------- gated rmsnorm: y = rmsnorm((y0+y1) * silu(gate)) * w, float4 ---------
__global__ void __launch_bounds__(256) grms_kernel(
    float* __restrict__ yout, const float* __restrict__ y0p, const float* __restrict__ y1p,
    const float* __restrict__ proj, const float* __restrict__ w)
{
    int row = blockIdx.x;
    const float4* y0r = reinterpret_cast<const float4*>(y0p + (size_t)row * I_);
    const float4* y1r = reinterpret_cast<const float4*>(y1p + (size_t)row * I_);
    const float4* gr = reinterpret_cast<const float4*>(proj + (size_t)row * PROJ_);
    float4 v[2];
    float ss = 0.f;
    #pragma unroll
    for (int k = 0; k < 2; k++) {
        int i = threadIdx.x + k * 256;
        float4 a = y0r[i], b = y1r[i], g = gr[i];
        v[k].x = (a.x + b.x) * siluf(g.x);
        v[k].y = (a.y + b.y) * siluf(g.y);
        v[k].z = (a.z + b.z) * siluf(g.z);
        v[k].w = (a.w + b.w) * siluf(g.w);
        ss += v[k].x * v[k].x + v[k].y * v[k].y + v[k].z * v[k].z + v[k].w * v[k].w;
    }
    float tot = block_reduce_sum(ss);
    float r = rsqrtf(tot * (1.f / (float)I_) + 1e-6f);
    #pragma unroll
    for (int k = 0; k < 2; k++) {
        int i = threadIdx.x + k * 256;
        float4 wv = reinterpret_cast<const float4*>(w)[i];
        float4 o;
        o.x = v[k].x * r * wv.x; o.y = v[k].y * r * wv.y;
        o.z = v[k].z * r * wv.z; o.w = v[k].w * r * wv.w;
        reinterpret_cast<float4*>(yout + (size_t)row * I_)[i] = o;
    }
}

// ---------------- host launcher ----------------
extern "C" void kernel_launch(void* const* d_in, const int* in_sizes, int n_in,
                              void* d_out, int out_size)
{
    const float* x        = (const float*)d_in[0];
    const float* in_w     = (const float*)d_in[1];
    const float* in_b     = (const float*)d_in[2];
    const float* norm_w   = (const float*)d_in[3];
    const float* mix_in_w = (const float*)d_in[4];
    const float* conv_w   = (const float*)d_in[5];
    const float* conv_b   = (const float*)d_in[6];
    const float* dt_bias  = (const float*)d_in[7];
    const float* A_log    = (const float*)d_in[8];
    const float* Dvec     = (const float*)d_in[9];
    const float* gnorm_w  = (const float*)d_in[10];
    const float* mix_out_w= (const float*)d_in[11];
    const float* out_w    = (const float*)d_in[12];
    const float* out_b    = (const float*)d_in[13];
    const float* code_w   = (const float*)d_in[14];
    const float* code_b   = (const float*)d_in[15];
    float* out = (float*)d_out;

    float *h, *hn, *proj, *yb;
    cudaGetSymbolAddress((void**)&h,    g_h);
    cudaGetSymbolAddress((void**)&hn,   g_hn);
    cudaGetSymbolAddress((void**)&proj, g_proj);
    cudaGetSymbolAddress((void**)&yb,   g_y);
    float* yb0 = yb;
    float* yb1 = yb + (size_t)BT * I_;

    cudaFuncSetAttribute(gemm_tc, cudaFuncAttributeMaxDynamicSharedMemorySize, GEMM_SMEM);

    // h = x @ in_w + in_b
    gemm_tc<<<dim3(D_ / 128, BT / 128), 256, GEMM_SMEM>>>(x, in_w, h, BT, D_, IN_, in_b, 0);

    for (int l = 0; l < L_; l++) {
        rmsnorm_kernel<<<BT, 256>>>(h, norm_w + l * D_, hn);
        gemm_tc<<<dim3((PROJ_ + 127) / 128, BT / 128), 256, GEMM_SMEM>>>(
            hn, mix_in_w + (size_t)l * D_ * PROJ_, proj, BT, PROJ_, D_, nullptr, 0);
        scan_p1<<<2 * CC * B_ * H_, 128>>>(
            proj, conv_w + (size_t)l * K_ * CONV_, conv_b + (size_t)l * CONV_,
            dt_bias + l * H_, A_log + l * H_);
        scan_p2<<<2 * B_ * H_, 128>>>(A_log + l * H_);
        scan_p3<<<2 * CC * B_ * H_, 128>>>(
            proj, conv_w + (size_t)l * K_ * CONV_, conv_b + (size_t)l * CONV_,
            dt_bias + l * H_, A_log + l * H_, Dvec + l * H_, yb);
        grms_kernel<<<BT, 256>>>(yb0, yb0, yb1, proj, gnorm_w + (size_t)l * I_);
        gemm_tc<<<dim3(D_ / 128, BT / 128), 256, GEMM_SMEM>>>(
            yb0, mix_out_w + (size_t)l * I_ * D_, h, BT, D_, I_, nullptr, 1);
    }

    // heads
    gemm_tc<<<dim3(OUT_ / 128, BT / 128), 256, GEMM_SMEM>>>(h, out_w, out, BT, OUT_, D_, out_b, 0);
    gemm_tc<<<dim3(CB_ / 128, BT / 128), 256, GEMM_SMEM>>>(
        h, code_w, out + (size_t)BT * OUT_, BT, CB_, D_, code_b, 0);
}

// round 15
// speedup vs baseline: 1.1424x; 1.0560x over previous
#include <cuda_runtime.h>
#include <cuda_bf16.h>
#include <math.h>
#include <stdint.h>

// ---------------- dimensions ----------------
#define B_   8
#define T_   1024
#define BT   8192           // B_*T_
#define IN_  512
#define D_   1024
#define I_   2048
#define N_   64
#define H_   16
#define P_   128
#define K_   3
#define L_   4
#define OUT_ 512
#define CB_  1024
#define CONV_ 2176          // I_ + 2*N_
#define PROJ_ 4240          // I_ + CONV_ + H_
#define CC   8              // scan chunks
#define TC   128            // T_/CC
#define CH_STRIDE 4096      // P_*32 floats per state slot

// ---------------- device scratch (no allocation allowed) ----------------
__device__ float g_h[(size_t)BT * D_];
__device__ float g_hn[(size_t)BT * D_];
__device__ float g_proj[(size_t)BT * PROJ_];
__device__ float g_y[2][(size_t)BT * I_];   // two N-half partials
__device__ float g_state[(size_t)2 * B_ * H_ * CC * CH_STRIDE];  // chunk states
__device__ float g_dts[B_ * H_ * CC];       // per-chunk dt sums

// ---------------- helpers ----------------
__device__ __forceinline__ float warp_reduce_sum(float v) {
    #pragma unroll
    for (int o = 16; o; o >>= 1) v += __shfl_xor_sync(0xffffffffu, v, o);
    return v;
}

__device__ __forceinline__ float siluf(float x) {
    return x / (1.f + __expf(-x));
}

// split two fp32 values into packed bf16x2 hi + bf16x2 lo (v0 in low half)
__device__ __forceinline__ void split_bf16_pair(float v0, float v1, uint32_t& hi, uint32_t& lo) {
    __nv_bfloat162 h = __floats2bfloat162_rn(v0, v1);
    float h0 = __bfloat162float(h.x);
    float h1 = __bfloat162float(h.y);
    __nv_bfloat162 l = __floats2bfloat162_rn(v0 - h0, v1 - h1);
    hi = *reinterpret_cast<uint32_t*>(&h);
    lo = *reinterpret_cast<uint32_t*>(&l);
}

__device__ __forceinline__ void mma_bf16(float* d, const uint32_t* a, const uint32_t* b) {
    asm volatile(
        "mma.sync.aligned.m16n8k16.row.col.f32.bf16.bf16.f32 "
        "{%0,%1,%2,%3}, {%4,%5,%6,%7}, {%8,%9}, {%0,%1,%2,%3};"
        : "+f"(d[0]), "+f"(d[1]), "+f"(d[2]), "+f"(d[3])
        : "r"(a[0]), "r"(a[1]), "r"(a[2]), "r"(a[3]), "r"(b[0]), "r"(b[1]));
}

// ---------------- split-bf16 (bf16x3) tensor-core GEMM (R7 config) ----------
#define ASTR2 20
#define BSTR2 136
#define A_BUF (128 * ASTR2)
#define B_BUF (16 * BSTR2)
#define GEMM_SMEM ((4 * A_BUF + 4 * B_BUF) * 4)

__global__ void __launch_bounds__(256) gemm_tc(
    const float* __restrict__ A, const float* __restrict__ Bm,
    float* __restrict__ C, int M, int N, int K,
    const float* __restrict__ bias, int accum)
{
    extern __shared__ uint32_t smem[];
    uint32_t* AsH = smem;
    uint32_t* AsL = AsH + 2 * A_BUF;
    uint32_t* BsH = AsL + 2 * A_BUF;
    uint32_t* BsL = BsH + 2 * B_BUF;

    const int tid = threadIdx.x;
    const int lane = tid & 31;
    const int warp = tid >> 5;
    const int warpM = warp >> 1;
    const int warpN = warp & 1;
    const int gid = lane >> 2;
    const int tid4 = lane & 3;

    const int m0 = blockIdx.y * 128;
    const int n0 = blockIdx.x * 128;

    const int a_row = tid >> 3;
    const int a_k4 = (tid & 7) * 4;
    const int b_n4 = lane * 4;

    float acc[2][8][4];
    #pragma unroll
    for (int i = 0; i < 2; i++)
        #pragma unroll
        for (int j = 0; j < 8; j++)
            #pragma unroll
            for (int c = 0; c < 4; c++) acc[i][j][c] = 0.f;

    float4 pa[4];
    float4 pb[4];
    const bool edge = (n0 + 128 > N);

    auto loadAB = [&](int kt) {
        const int kbase = kt * 32;
        #pragma unroll
        for (int i = 0; i < 4; i++)
            pa[i] = *reinterpret_cast<const float4*>(
                A + (size_t)(m0 + a_row + 32 * i) * K + kbase + a_k4);
        const int n = n0 + b_n4;
        #pragma unroll
        for (int i = 0; i < 2; i++) {
            const int kp = warp + 8 * i;
            #pragma unroll
            for (int r = 0; r < 2; r++) {
                const size_t off = (size_t)(kbase + 2 * kp + r) * N;
                float4 v;
                if (!edge) {
                    v = *reinterpret_cast<const float4*>(Bm + off + n);
                } else {
                    v.x = (n + 0 < N) ? Bm[off + n + 0] : 0.f;
                    v.y = (n + 1 < N) ? Bm[off + n + 1] : 0.f;
                    v.z = (n + 2 < N) ? Bm[off + n + 2] : 0.f;
                    v.w = (n + 3 < N) ? Bm[off + n + 3] : 0.f;
                }
                pb[2 * i + r] = v;
            }
        }
    };

    auto smemStore = [&](int buf) {
        uint32_t* ah = AsH + buf * A_BUF;
        uint32_t* al = AsL + buf * A_BUF;
        #pragma unroll
        for (int i = 0; i < 4; i++) {
            const int m = a_row + 32 * i;
            uint2 h2, l2;
            split_bf16_pair(pa[i].x, pa[i].y, h2.x, l2.x);
            split_bf16_pair(pa[i].z, pa[i].w, h2.y, l2.y);
            const int idx = m * ASTR2 + (a_k4 >> 1);
            *reinterpret_cast<uint2*>(ah + idx) = h2;
            *reinterpret_cast<uint2*>(al + idx) = l2;
        }
        uint32_t* bh = BsH + buf * B_BUF;
        uint32_t* bl = BsL + buf * B_BUF;
        #pragma unroll
        for (int i = 0; i < 2; i++) {
            const int kp = warp + 8 * i;
            const float4 r0 = pb[2 * i];
            const float4 r1 = pb[2 * i + 1];
            uint4 h4, l4;
            split_bf16_pair(r0.x, r1.x, h4.x, l4.x);
            split_bf16_pair(r0.y, r1.y, h4.y, l4.y);
            split_bf16_pair(r0.z, r1.z, h4.z, l4.z);
            split_bf16_pair(r0.w, r1.w, h4.w, l4.w);
            const int idx = kp * BSTR2 + b_n4;
            *reinterpret_cast<uint4*>(bh + idx) = h4;
            *reinterpret_cast<uint4*>(bl + idx) = l4;
        }
    };

    auto compute = [&](int buf) {
        const uint32_t* ah_s = AsH + buf * A_BUF;
        const uint32_t* al_s = AsL + buf * A_BUF;
        const uint32_t* bh_s = BsH + buf * B_BUF;
        const uint32_t* bl_s = BsL + buf * B_BUF;
        #pragma unroll
        for (int ks = 0; ks < 2; ks++) {
            const int kp0 = ks * 8;
            uint32_t ah[2][4], al[2][4], bh[8][2], bl[8][2];
            #pragma unroll
            for (int mf = 0; mf < 2; mf++) {
                const int m = warpM * 32 + mf * 16 + gid;
                const int i0 = m * ASTR2 + kp0 + tid4;
                const int i1 = (m + 8) * ASTR2 + kp0 + tid4;
                ah[mf][0] = ah_s[i0];     al[mf][0] = al_s[i0];
                ah[mf][1] = ah_s[i1];     al[mf][1] = al_s[i1];
                ah[mf][2] = ah_s[i0 + 4]; al[mf][2] = al_s[i0 + 4];
                ah[mf][3] = ah_s[i1 + 4]; al[mf][3] = al_s[i1 + 4];
            }
            #pragma unroll
            for (int nf = 0; nf < 8; nf++) {
                const int n = warpN * 64 + nf * 8 + gid;
                const int i0 = (kp0 + tid4) * BSTR2 + n;
                const int i1 = (kp0 + tid4 + 4) * BSTR2 + n;
                bh[nf][0] = bh_s[i0]; bl[nf][0] = bl_s[i0];
                bh[nf][1] = bh_s[i1]; bl[nf][1] = bl_s[i1];
            }
            #pragma unroll
            for (int mf = 0; mf < 2; mf++)
                #pragma unroll
                for (int nf = 0; nf < 8; nf++) {
                    mma_bf16(acc[mf][nf], ah[mf], bh[nf]);
                    mma_bf16(acc[mf][nf], al[mf], bh[nf]);
                    mma_bf16(acc[mf][nf], ah[mf], bl[nf]);
                }
        }
    };

    const int nk = K >> 5;
    loadAB(0);
    smemStore(0);
    __syncthreads();
    for (int kt = 0; kt < nk; kt++) {
        const int buf = kt & 1;
        if (kt + 1 < nk) loadAB(kt + 1);
        compute(buf);
        if (kt + 1 < nk) smemStore(buf ^ 1);
        __syncthreads();
    }

    #pragma unroll
    for (int mf = 0; mf < 2; mf++) {
        #pragma unroll
        for (int nf = 0; nf < 8; nf++) {
            const int n = n0 + warpN * 64 + nf * 8 + tid4 * 2;
            if (n >= N) continue;
            float bv0 = 0.f, bv1 = 0.f;
            if (bias) { bv0 = bias[n]; bv1 = bias[n + 1]; }
            #pragma unroll
            for (int h = 0; h < 2; h++) {
                const int m = m0 + warpM * 32 + mf * 16 + gid + h * 8;
                float v0 = acc[mf][nf][2 * h]     + bv0;
                float v1 = acc[mf][nf][2 * h + 1] + bv1;
                const size_t idx = (size_t)m * N + n;
                if (accum) { v0 += C[idx]; v1 += C[idx + 1]; }
                C[idx] = v0;
                C[idx + 1] = v1;
            }
        }
    }
}

// ------- rmsnorm (D_=1024): warp per row, no block barriers -----------------
__global__ void __launch_bounds__(256) rmsnorm_kernel(
    const float* __restrict__ x, const float* __restrict__ w, float* __restrict__ out)
{
    const int lane = threadIdx.x & 31;
    const int row = blockIdx.x * 8 + (threadIdx.x >> 5);
    const float4* xr = reinterpret_cast<const float4*>(x + (size_t)row * D_);
    const float4* wr = reinterpret_cast<const float4*>(w);
    float4* orow = reinterpret_cast<float4*>(out + (size_t)row * D_);
    float4 v[8];
    float ss = 0.f;
    #pragma unroll
    for (int k = 0; k < 8; k++) {
        v[k] = xr[lane + 32 * k];
        ss += v[k].x * v[k].x + v[k].y * v[k].y + v[k].z * v[k].z + v[k].w * v[k].w;
    }
    float tot = warp_reduce_sum(ss);
    float r = rsqrtf(tot * (1.f / (float)D_) + 1e-6f);
    #pragma unroll
    for (int k = 0; k < 8; k++) {
        float4 wv = wr[lane + 32 * k];
        float4 o;
        o.x = v[k].x * r * wv.x; o.y = v[k].y * r * wv.y;
        o.z = v[k].z * r * wv.z; o.w = v[k].w * r * wv.w;
        orow[lane + 32 * k] = o;
    }
}

// ======================= chunk-parallel SSM scan ============================
// Phase 1: per (half, b, h, chunk) CTA, scan TC steps from s=0, store final
// local state + chunk dt-sum. Conv inline, unroll x4.
__global__ void __launch_bounds__(128) scan_p1(
    const float* __restrict__ proj, const float* __restrict__ cw,
    const float* __restrict__ cb, const float* __restrict__ dt_bias,
    const float* __restrict__ A_log)
{
    const int bi = blockIdx.x;
    const int half = bi >> 10;
    const int c = (bi >> 7) & 7;
    const int b = (bi >> 4) & 7;
    const int h = bi & 15;
    const int p = threadIdx.x;
    const int n_off = half * 32;
    const int t0 = c * TC;

    __shared__ float sB[4][32], sDT[4];

    const float a = -__expf(A_log[h]);
    const float dtb_h = dt_bias[h];

    const int xch = h * P_ + p;
    const float xw0 = cw[xch], xw1 = cw[CONV_ + xch], xw2 = cw[2 * CONV_ + xch];
    const float xbias = cb[xch];
    const int xcol = I_ + xch;

    float bw0 = 0.f, bw1 = 0.f, bw2 = 0.f, bcbias = 0.f;
    int bccol = xcol;
    if (p < 32) {
        const int bcch = I_ + n_off + p;
        bw0 = cw[bcch]; bw1 = cw[CONV_ + bcch]; bw2 = cw[2 * CONV_ + bcch];
        bcbias = cb[bcch];
        bccol = I_ + bcch;
    }
    const int dtcol = I_ + CONV_ + h;

    const float* prow = proj + (size_t)b * T_ * PROJ_;

    float hx1 = 0.f, hx2 = 0.f, hb1 = 0.f, hb2 = 0.f;
    if (c > 0) {
        hx1 = prow[(size_t)(t0 - 1) * PROJ_ + xcol];
        hx2 = prow[(size_t)(t0 - 2) * PROJ_ + xcol];
        if (p < 32) {
            hb1 = prow[(size_t)(t0 - 1) * PROJ_ + bccol];
            hb2 = prow[(size_t)(t0 - 2) * PROJ_ + bccol];
        }
    }

    float s[32];
    #pragma unroll
    for (int n = 0; n < 32; n++) s[n] = 0.f;
    float dtsum = 0.f;

    for (int t = t0; t < t0 + TC; t += 4) {
        const float* r0 = prow + (size_t)t * PROJ_;
        float xr[4], bc[4];
        #pragma unroll
        for (int j = 0; j < 4; j++) xr[j] = r0[(size_t)j * PROJ_ + xcol];
        if (p < 32) {
            #pragma unroll
            for (int j = 0; j < 4; j++) bc[j] = r0[(size_t)j * PROJ_ + bccol];
        }
        if (p >= 64 && p < 68) {
            const int j = p - 64;
            float v = r0[(size_t)j * PROJ_ + dtcol] + dtb_h;
            sDT[j] = (v > 20.f) ? v : log1pf(__expf(v));
        }
        float xs[4];
        xs[0] = siluf(xbias + xr[0] * xw2 + hx1 * xw1 + hx2 * xw0);
        xs[1] = siluf(xbias + xr[1] * xw2 + xr[0] * xw1 + hx1 * xw0);
        xs[2] = siluf(xbias + xr[2] * xw2 + xr[1] * xw1 + xr[0] * xw0);
        xs[3] = siluf(xbias + xr[3] * xw2 + xr[2] * xw1 + xr[1] * xw0);
        hx2 = xr[2]; hx1 = xr[3];
        if (p < 32) {
            sB[0][p] = siluf(bcbias + bc[0] * bw2 + hb1 * bw1 + hb2 * bw0);
            sB[1][p] = siluf(bcbias + bc[1] * bw2 + bc[0] * bw1 + hb1 * bw0);
            sB[2][p] = siluf(bcbias + bc[2] * bw2 + bc[1] * bw1 + bc[0] * bw0);
            sB[3][p] = siluf(bcbias + bc[3] * bw2 + bc[2] * bw1 + bc[1] * bw0);
            hb2 = bc[2]; hb1 = bc[3];
        }
        __syncthreads();
        float dA[4], k[4];
        #pragma unroll
        for (int j = 0; j < 4; j++) {
            const float dtj = sDT[j];
            dtsum += dtj;
            dA[j] = __expf(dtj * a);
            k[j] = dtj * xs[j];
        }
        #pragma unroll
        for (int n = 0; n < 32; n++) {
            float sv = s[n];
            sv = sv * dA[0] + k[0] * sB[0][n];
            sv = sv * dA[1] + k[1] * sB[1][n];
            sv = sv * dA[2] + k[2] * sB[2][n];
            sv = sv * dA[3] + k[3] * sB[3][n];
            s[n] = sv;
        }
        __syncthreads();
    }

    const size_t sbase = ((((size_t)half * B_ + b) * H_ + h) * CC + c) * CH_STRIDE;
    #pragma unroll
    for (int n = 0; n < 32; n++)
        g_state[sbase + n * 128 + p] = s[n];
    if (half == 0 && p == 64)
        g_dts[(b * H_ + h) * CC + c] = dtsum;
}

// Phase 2: convert local final states -> true chunk-initial states (in place).
__global__ void __launch_bounds__(128) scan_p2(const float* __restrict__ A_log)
{
    const int bi = blockIdx.x;               // [0, 256)
    const int half = bi >> 7;
    const int b = (bi >> 4) & 7;
    const int h = bi & 15;
    const int p = threadIdx.x;
    const float a = -__expf(A_log[h]);

    float s[32];
    #pragma unroll
    for (int n = 0; n < 32; n++) s[n] = 0.f;

    const size_t base0 = (((size_t)half * B_ + b) * H_ + h) * CC * CH_STRIDE;
    for (int c = 0; c < CC; c++) {
        const float D = __expf(a * g_dts[(b * H_ + h) * CC + c]);
        const size_t sb = base0 + (size_t)c * CH_STRIDE;
        #pragma unroll
        for (int n = 0; n < 32; n++) {
            const size_t idx = sb + n * 128 + p;
            const float local = g_state[idx];
            g_state[idx] = s[n];
            s[n] = s[n] * D + local;
        }
    }
}

// Phase 3: rescan each chunk from its true initial state, emit y. Unroll x4.
__global__ void __launch_bounds__(128) scan_p3(
    const float* __restrict__ proj, const float* __restrict__ cw,
    const float* __restrict__ cb, const float* __restrict__ dt_bias,
    const float* __restrict__ A_log, const float* __restrict__ Dv,
    float* __restrict__ y)
{
    const int bi = blockIdx.x;
    const int half = bi >> 10;
    const int c = (bi >> 7) & 7;
    const int b = (bi >> 4) & 7;
    const int h = bi & 15;
    const int p = threadIdx.x;
    const int n_off = half * 32;
    const int t0 = c * TC;

    __shared__ float sB[4][32], sC[4][32], sDT[4];

    const float a = -__expf(A_log[h]);
    const float dcoef = (half == 0) ? Dv[h] : 0.f;
    const float dtb_h = dt_bias[h];

    const int xch = h * P_ + p;
    const float xw0 = cw[xch], xw1 = cw[CONV_ + xch], xw2 = cw[2 * CONV_ + xch];
    const float xbias = cb[xch];
    const int xcol = I_ + xch;

    float bw0 = 0.f, bw1 = 0.f, bw2 = 0.f, bcbias = 0.f;
    int bccol = xcol;
    if (p < 64) {
        const int bcch = I_ + ((p < 32) ? (n_off + p) : (N_ + n_off + (p - 32)));
        bw0 = cw[bcch]; bw1 = cw[CONV_ + bcch]; bw2 = cw[2 * CONV_ + bcch];
        bcbias = cb[bcch];
        bccol = I_ + bcch;
    }
    const int dtcol = I_ + CONV_ + h;

    const float* prow = proj + (size_t)b * T_ * PROJ_;

    float hx1 = 0.f, hx2 = 0.f, hb1 = 0.f, hb2 = 0.f;
    if (c > 0) {
        hx1 = prow[(size_t)(t0 - 1) * PROJ_ + xcol];
        hx2 = prow[(size_t)(t0 - 2) * PROJ_ + xcol];
        if (p < 64) {
            hb1 = prow[(size_t)(t0 - 1) * PROJ_ + bccol];
            hb2 = prow[(size_t)(t0 - 2) * PROJ_ + bccol];
        }
    }

    float s[32];
    const size_t sbase = ((((size_t)half * B_ + b) * H_ + h) * CC + c) * CH_STRIDE;
    #pragma unroll
    for (int n = 0; n < 32; n++)
        s[n] = g_state[sbase + n * 128 + p];

    float* yb = y + (size_t)half * BT * I_ + (size_t)b * T_ * I_ + h * P_ + p;

    for (int t = t0; t < t0 + TC; t += 4) {
        const float* r0 = prow + (size_t)t * PROJ_;
        float xr[4], bc[4];
        #pragma unroll
        for (int j = 0; j < 4; j++) xr[j] = r0[(size_t)j * PROJ_ + xcol];
        if (p < 64) {
            #pragma unroll
            for (int j = 0; j < 4; j++) bc[j] = r0[(size_t)j * PROJ_ + bccol];
        }
        if (p >= 64 && p < 68) {
            const int j = p - 64;
            float v = r0[(size_t)j * PROJ_ + dtcol] + dtb_h;
            sDT[j] = (v > 20.f) ? v : log1pf(__expf(v));
        }
        float xs[4];
        xs[0] = siluf(xbias + xr[0] * xw2 + hx1 * xw1 + hx2 * xw0);
        xs[1] = siluf(xbias + xr[1] * xw2 + xr[0] * xw1 + hx1 * xw0);
        xs[2] = siluf(xbias + xr[2] * xw2 + xr[1] * xw1 + xr[0] * xw0);
        xs[3] = siluf(xbias + xr[3] * xw2 + xr[2] * xw1 + xr[1] * xw0);
        hx2 = xr[2]; hx1 = xr[3];
        if (p < 32) {
            sB[0][p] = siluf(bcbias + bc[0] * bw2 + hb1 * bw1 + hb2 * bw0);
            sB[1][p] = siluf(bcbias + bc[1] * bw2 + bc[0] * bw1 + hb1 * bw0);
            sB[2][p] = siluf(bcbias + bc[2] * bw2 + bc[1] * bw1 + bc[0] * bw0);
            sB[3][p] = siluf(bcbias + bc[3] * bw2 + bc[2] * bw1 + bc[1] * bw0);
            hb2 = bc[2]; hb1 = bc[3];
        } else if (p < 64) {
            sC[0][p - 32] = siluf(bcbias + bc[0] * bw2 + hb1 * bw1 + hb2 * bw0);
            sC[1][p - 32] = siluf(bcbias + bc[1] * bw2 + bc[0] * bw1 + hb1 * bw0);
            sC[2][p - 32] = siluf(bcbias + bc[2] * bw2 + bc[1] * bw1 + bc[0] * bw0);
            sC[3][p - 32] = siluf(bcbias + bc[3] * bw2 + bc[2] * bw1 + bc[1] * bw0);
            hb2 = bc[2]; hb1 = bc[3];
        }
        __syncthreads();
        float dA[4], k[4];
        #pragma unroll
        for (int j = 0; j < 4; j++) {
            const float dtj = sDT[j];
            dA[j] = __expf(dtj * a);
            k[j] = dtj * xs[j];
        }
        float ya[4], ybv[4];
        #pragma unroll
        for (int j = 0; j < 4; j++) { ya[j] = 0.f; ybv[j] = 0.f; }
        #pragma unroll
        for (int n = 0; n < 32; n += 2) {
            #pragma unroll
            for (int j = 0; j < 4; j++) {
                s[n]     = s[n]     * dA[j] + k[j] * sB[j][n];     ya[j]  += s[n]     * sC[j][n];
                s[n + 1] = s[n + 1] * dA[j] + k[j] * sB[j][n + 1]; ybv[j] += s[n + 1] * sC[j][n + 1];
            }
        }
        #pragma unroll
        for (int j = 0; j < 4; j++)
            yb[(size_t)(t + j) * I_] = ya[j] + ybv[j] + dcoef * xs[j];
        __syncthreads();
    }
}

// ------- gated rmsnorm: warp per row, float4, no block barriers --------------
__global__ void __launch_bounds__(256) grms_kernel(
    float* __restrict__ yout, const float* __restrict__ y0p, const float* __restrict__ y1p,
    const float* __restrict__ proj, const float* __restrict__ w)
{
    const int lane = threadIdx.x & 31;
    const int row = blockIdx.x * 8 + (threadIdx.x >> 5);
    const float4* y0r = reinterpret_cast<const float4*>(y0p + (size_t)row * I_);
    const float4* y1r = reinterpret_cast<const float4*>(y1p + (size_t)row * I_);
    const float4* gr = reinterpret_cast<const float4*>(proj + (size_t)row * PROJ_);
    const float4* wr = reinterpret_cast<const float4*>(w);
    float4* orow = reinterpret_cast<float4*>(yout + (size_t)row * I_);
    float4 v[16];
    float ss = 0.f;
    #pragma unroll
    for (int k = 0; k < 16; k++) {
        const int i = lane + 32 * k;
        float4 a = y0r[i], b = y1r[i], g = gr[i];
        v[k].x = (a.x + b.x) * siluf(g.x);
        v[k].y = (a.y + b.y) * siluf(g.y);
        v[k].z = (a.z + b.z) * siluf(g.z);
        v[k].w = (a.w + b.w) * siluf(g.w);
        ss += v[k].x * v[k].x + v[k].y * v[k].y + v[k].z * v[k].z + v[k].w * v[k].w;
    }
    float tot = warp_reduce_sum(ss);
    float r = rsqrtf(tot * (1.f / (float)I_) + 1e-6f);
    #pragma unroll
    for (int k = 0; k < 16; k++) {
        const int i = lane + 32 * k;
        float4 wv = wr[i];
        float4 o;
        o.x = v[k].x * r * wv.x; o.y = v[k].y * r * wv.y;
        o.z = v[k].z * r * wv.z; o.w = v[k].w * r * wv.w;
        orow[i] = o;
    }
}

// ---------------- host launcher ----------------
extern "C" void kernel_launch(void* const* d_in, const int* in_sizes, int n_in,
                              void* d_out, int out_size)
{
    const float* x        = (const float*)d_in[0];
    const float* in_w     = (const float*)d_in[1];
    const float* in_b     = (const float*)d_in[2];
    const float* norm_w   = (const float*)d_in[3];
    const float* mix_in_w = (const float*)d_in[4];
    const float* conv_w   = (const float*)d_in[5];
    const float* conv_b   = (const float*)d_in[6];
    const float* dt_bias  = (const float*)d_in[7];
    const float* A_log    = (const float*)d_in[8];
    const float* Dvec     = (const float*)d_in[9];
    const float* gnorm_w  = (const float*)d_in[10];
    const float* mix_out_w= (const float*)d_in[11];
    const float* out_w    = (const float*)d_in[12];
    const float* out_b    = (const float*)d_in[13];
    const float* code_w   = (const float*)d_in[14];
    const float* code_b   = (const float*)d_in[15];
    float* out = (float*)d_out;

    float *h, *hn, *proj, *yb;
    cudaGetSymbolAddress((void**)&h,    g_h);
    cudaGetSymbolAddress((void**)&hn,   g_hn);
    cudaGetSymbolAddress((void**)&proj, g_proj);
    cudaGetSymbolAddress((void**)&yb,   g_y);
    float* yb0 = yb;
    float* yb1 = yb + (size_t)BT * I_;

    cudaFuncSetAttribute(gemm_tc, cudaFuncAttributeMaxDynamicSharedMemorySize, GEMM_SMEM);

    // h = x @ in_w + in_b
    gemm_tc<<<dim3(D_ / 128, BT / 128), 256, GEMM_SMEM>>>(x, in_w, h, BT, D_, IN_, in_b, 0);

    for (int l = 0; l < L_; l++) {
        rmsnorm_kernel<<<BT / 8, 256>>>(h, norm_w + l * D_, hn);
        gemm_tc<<<dim3((PROJ_ + 127) / 128, BT / 128), 256, GEMM_SMEM>>>(
            hn, mix_in_w + (size_t)l * D_ * PROJ_, proj, BT, PROJ_, D_, nullptr, 0);
        scan_p1<<<2 * CC * B_ * H_, 128>>>(
            proj, conv_w + (size_t)l * K_ * CONV_, conv_b + (size_t)l * CONV_,
            dt_bias + l * H_, A_log + l * H_);
        scan_p2<<<2 * B_ * H_, 128>>>(A_log + l * H_);
        scan_p3<<<2 * CC * B_ * H_, 128>>>(
            proj, conv_w + (size_t)l * K_ * CONV_, conv_b + (size_t)l * CONV_,
            dt_bias + l * H_, A_log + l * H_, Dvec + l * H_, yb);
        grms_kernel<<<BT / 8, 256>>>(yb0, yb0, yb1, proj, gnorm_w + (size_t)l * I_);
        gemm_tc<<<dim3(D_ / 128, BT / 128), 256, GEMM_SMEM>>>(
            yb0, mix_out_w + (size_t)l * I_ * D_, h, BT, D_, I_, nullptr, 1);
    }

    // heads
    gemm_tc<<<dim3(OUT_ / 128, BT / 128), 256, GEMM_SMEM>>>(h, out_w, out, BT, OUT_, D_, out_b, 0);
    gemm_tc<<<dim3(CB_ / 128, BT / 128), 256, GEMM_SMEM>>>(
        h, code_w, out + (size_t)BT * OUT_, BT, CB_, D_, code_b, 0);
}

// round 16
// speedup vs baseline: 1.1544x; 1.0105x over previous
#include <cuda_runtime.h>
#include <cuda_bf16.h>
#include <math.h>
#include <stdint.h>

// ---------------- dimensions ----------------
#define B_   8
#define T_   1024
#define BT   8192           // B_*T_
#define IN_  512
#define D_   1024
#define I_   2048
#define N_   64
#define H_   16
#define P_   128
#define K_   3
#define L_   4
#define OUT_ 512
#define CB_  1024
#define CONV_ 2176          // I_ + 2*N_
#define PROJ_ 4240          // I_ + CONV_ + H_
#define CC   8              // scan chunks
#define TC   128            // T_/CC
#define CH_STRIDE 4096      // P_*32 floats per state slot
#define BCD_STR 160         // per-row: B[64] C[64] dt[16] (+pad)

// ---------------- device scratch (no allocation allowed) ----------------
__device__ float g_h[(size_t)BT * D_];
__device__ float g_hn[(size_t)BT * D_];
__device__ float g_proj[(size_t)BT * PROJ_];
__device__ float g_y[2][(size_t)BT * I_];   // two N-half partials
__device__ float g_state[(size_t)2 * B_ * H_ * CC * CH_STRIDE];  // chunk states
__device__ float g_bcd[(size_t)BT * BCD_STR];   // conv'd B,C + softplus dt
__device__ float g_cumdt[B_ * H_ * T_];         // per-chunk cumulative dt

// ---------------- helpers ----------------
__device__ __forceinline__ float warp_reduce_sum(float v) {
    #pragma unroll
    for (int o = 16; o; o >>= 1) v += __shfl_xor_sync(0xffffffffu, v, o);
    return v;
}

__device__ __forceinline__ float siluf(float x) {
    return x / (1.f + __expf(-x));
}

// split two fp32 values into packed bf16x2 hi + bf16x2 lo (v0 in low half)
__device__ __forceinline__ void split_bf16_pair(float v0, float v1, uint32_t& hi, uint32_t& lo) {
    __nv_bfloat162 h = __floats2bfloat162_rn(v0, v1);
    float h0 = __bfloat162float(h.x);
    float h1 = __bfloat162float(h.y);
    __nv_bfloat162 l = __floats2bfloat162_rn(v0 - h0, v1 - h1);
    hi = *reinterpret_cast<uint32_t*>(&h);
    lo = *reinterpret_cast<uint32_t*>(&l);
}

__device__ __forceinline__ void mma_bf16(float* d, const uint32_t* a, const uint32_t* b) {
    asm volatile(
        "mma.sync.aligned.m16n8k16.row.col.f32.bf16.bf16.f32 "
        "{%0,%1,%2,%3}, {%4,%5,%6,%7}, {%8,%9}, {%0,%1,%2,%3};"
        : "+f"(d[0]), "+f"(d[1]), "+f"(d[2]), "+f"(d[3])
        : "r"(a[0]), "r"(a[1]), "r"(a[2]), "r"(a[3]), "r"(b[0]), "r"(b[1]));
}

// ---------------- split-bf16 (bf16x3) tensor-core GEMM (R7 config) ----------
#define ASTR2 20
#define BSTR2 136
#define A_BUF (128 * ASTR2)
#define B_BUF (16 * BSTR2)
#define GEMM_SMEM ((4 * A_BUF + 4 * B_BUF) * 4)

__global__ void __launch_bounds__(256) gemm_tc(
    const float* __restrict__ A, const float* __restrict__ Bm,
    float* __restrict__ C, int M, int N, int K,
    const float* __restrict__ bias, int accum)
{
    extern __shared__ uint32_t smem[];
    uint32_t* AsH = smem;
    uint32_t* AsL = AsH + 2 * A_BUF;
    uint32_t* BsH = AsL + 2 * A_BUF;
    uint32_t* BsL = BsH + 2 * B_BUF;

    const int tid = threadIdx.x;
    const int lane = tid & 31;
    const int warp = tid >> 5;
    const int warpM = warp >> 1;
    const int warpN = warp & 1;
    const int gid = lane >> 2;
    const int tid4 = lane & 3;

    const int m0 = blockIdx.y * 128;
    const int n0 = blockIdx.x * 128;

    const int a_row = tid >> 3;
    const int a_k4 = (tid & 7) * 4;
    const int b_n4 = lane * 4;

    float acc[2][8][4];
    #pragma unroll
    for (int i = 0; i < 2; i++)
        #pragma unroll
        for (int j = 0; j < 8; j++)
            #pragma unroll
            for (int c = 0; c < 4; c++) acc[i][j][c] = 0.f;

    float4 pa[4];
    float4 pb[4];
    const bool edge = (n0 + 128 > N);

    auto loadAB = [&](int kt) {
        const int kbase = kt * 32;
        #pragma unroll
        for (int i = 0; i < 4; i++)
            pa[i] = *reinterpret_cast<const float4*>(
                A + (size_t)(m0 + a_row + 32 * i) * K + kbase + a_k4);
        const int n = n0 + b_n4;
        #pragma unroll
        for (int i = 0; i < 2; i++) {
            const int kp = warp + 8 * i;
            #pragma unroll
            for (int r = 0; r < 2; r++) {
                const size_t off = (size_t)(kbase + 2 * kp + r) * N;
                float4 v;
                if (!edge) {
                    v = *reinterpret_cast<const float4*>(Bm + off + n);
                } else {
                    v.x = (n + 0 < N) ? Bm[off + n + 0] : 0.f;
                    v.y = (n + 1 < N) ? Bm[off + n + 1] : 0.f;
                    v.z = (n + 2 < N) ? Bm[off + n + 2] : 0.f;
                    v.w = (n + 3 < N) ? Bm[off + n + 3] : 0.f;
                }
                pb[2 * i + r] = v;
            }
        }
    };

    auto smemStore = [&](int buf) {
        uint32_t* ah = AsH + buf * A_BUF;
        uint32_t* al = AsL + buf * A_BUF;
        #pragma unroll
        for (int i = 0; i < 4; i++) {
            const int m = a_row + 32 * i;
            uint2 h2, l2;
            split_bf16_pair(pa[i].x, pa[i].y, h2.x, l2.x);
            split_bf16_pair(pa[i].z, pa[i].w, h2.y, l2.y);
            const int idx = m * ASTR2 + (a_k4 >> 1);
            *reinterpret_cast<uint2*>(ah + idx) = h2;
            *reinterpret_cast<uint2*>(al + idx) = l2;
        }
        uint32_t* bh = BsH + buf * B_BUF;
        uint32_t* bl = BsL + buf * B_BUF;
        #pragma unroll
        for (int i = 0; i < 2; i++) {
            const int kp = warp + 8 * i;
            const float4 r0 = pb[2 * i];
            const float4 r1 = pb[2 * i + 1];
            uint4 h4, l4;
            split_bf16_pair(r0.x, r1.x, h4.x, l4.x);
            split_bf16_pair(r0.y, r1.y, h4.y, l4.y);
            split_bf16_pair(r0.z, r1.z, h4.z, l4.z);
            split_bf16_pair(r0.w, r1.w, h4.w, l4.w);
            const int idx = kp * BSTR2 + b_n4;
            *reinterpret_cast<uint4*>(bh + idx) = h4;
            *reinterpret_cast<uint4*>(bl + idx) = l4;
        }
    };

    auto compute = [&](int buf) {
        const uint32_t* ah_s = AsH + buf * A_BUF;
        const uint32_t* al_s = AsL + buf * A_BUF;
        const uint32_t* bh_s = BsH + buf * B_BUF;
        const uint32_t* bl_s = BsL + buf * B_BUF;
        #pragma unroll
        for (int ks = 0; ks < 2; ks++) {
            const int kp0 = ks * 8;
            uint32_t ah[2][4], al[2][4], bh[8][2], bl[8][2];
            #pragma unroll
            for (int mf = 0; mf < 2; mf++) {
                const int m = warpM * 32 + mf * 16 + gid;
                const int i0 = m * ASTR2 + kp0 + tid4;
                const int i1 = (m + 8) * ASTR2 + kp0 + tid4;
                ah[mf][0] = ah_s[i0];     al[mf][0] = al_s[i0];
                ah[mf][1] = ah_s[i1];     al[mf][1] = al_s[i1];
                ah[mf][2] = ah_s[i0 + 4]; al[mf][2] = al_s[i0 + 4];
                ah[mf][3] = ah_s[i1 + 4]; al[mf][3] = al_s[i1 + 4];
            }
            #pragma unroll
            for (int nf = 0; nf < 8; nf++) {
                const int n = warpN * 64 + nf * 8 + gid;
                const int i0 = (kp0 + tid4) * BSTR2 + n;
                const int i1 = (kp0 + tid4 + 4) * BSTR2 + n;
                bh[nf][0] = bh_s[i0]; bl[nf][0] = bl_s[i0];
                bh[nf][1] = bh_s[i1]; bl[nf][1] = bl_s[i1];
            }
            #pragma unroll
            for (int mf = 0; mf < 2; mf++)
                #pragma unroll
                for (int nf = 0; nf < 8; nf++) {
                    mma_bf16(acc[mf][nf], ah[mf], bh[nf]);
                    mma_bf16(acc[mf][nf], al[mf], bh[nf]);
                    mma_bf16(acc[mf][nf], ah[mf], bl[nf]);
                }
        }
    };

    const int nk = K >> 5;
    loadAB(0);
    smemStore(0);
    __syncthreads();
    for (int kt = 0; kt < nk; kt++) {
        const int buf = kt & 1;
        if (kt + 1 < nk) loadAB(kt + 1);
        compute(buf);
        if (kt + 1 < nk) smemStore(buf ^ 1);
        __syncthreads();
    }

    #pragma unroll
    for (int mf = 0; mf < 2; mf++) {
        #pragma unroll
        for (int nf = 0; nf < 8; nf++) {
            const int n = n0 + warpN * 64 + nf * 8 + tid4 * 2;
            if (n >= N) continue;
            float bv0 = 0.f, bv1 = 0.f;
            if (bias) { bv0 = bias[n]; bv1 = bias[n + 1]; }
            #pragma unroll
            for (int h = 0; h < 2; h++) {
                const int m = m0 + warpM * 32 + mf * 16 + gid + h * 8;
                float v0 = acc[mf][nf][2 * h]     + bv0;
                float v1 = acc[mf][nf][2 * h + 1] + bv1;
                const size_t idx = (size_t)m * N + n;
                if (accum) { v0 += C[idx]; v1 += C[idx + 1]; }
                C[idx] = v0;
                C[idx + 1] = v1;
            }
        }
    }
}

// ------- rmsnorm (D_=1024): warp per row, no block barriers -----------------
__global__ void __launch_bounds__(256) rmsnorm_kernel(
    const float* __restrict__ x, const float* __restrict__ w, float* __restrict__ out)
{
    const int lane = threadIdx.x & 31;
    const int row = blockIdx.x * 8 + (threadIdx.x >> 5);
    const float4* xr = reinterpret_cast<const float4*>(x + (size_t)row * D_);
    const float4* wr = reinterpret_cast<const float4*>(w);
    float4* orow = reinterpret_cast<float4*>(out + (size_t)row * D_);
    float4 v[8];
    float ss = 0.f;
    #pragma unroll
    for (int k = 0; k < 8; k++) {
        v[k] = xr[lane + 32 * k];
        ss += v[k].x * v[k].x + v[k].y * v[k].y + v[k].z * v[k].z + v[k].w * v[k].w;
    }
    float tot = warp_reduce_sum(ss);
    float r = rsqrtf(tot * (1.f / (float)D_) + 1e-6f);
    #pragma unroll
    for (int k = 0; k < 8; k++) {
        float4 wv = wr[lane + 32 * k];
        float4 o;
        o.x = v[k].x * r * wv.x; o.y = v[k].y * r * wv.y;
        o.z = v[k].z * r * wv.z; o.w = v[k].w * r * wv.w;
        orow[lane + 32 * k] = o;
    }
}

// ------- precompute conv'd B,C (+silu) and softplus dt, compact buffer -------
// g_bcd[row][0:64)=B, [64:128)=C, [128:144)=dt. h-independent -> computed once.
__global__ void __launch_bounds__(160) bcd_kernel(
    const float* __restrict__ proj, const float* __restrict__ cw,
    const float* __restrict__ cb, const float* __restrict__ dt_bias)
{
    const int c = threadIdx.x;
    const int row = blockIdx.x;
    const int t = row & (T_ - 1);
    float* o = g_bcd + (size_t)row * BCD_STR;
    if (c < 128) {
        const int ch = I_ + c;                         // conv channel of B/C
        const float* pr = proj + (size_t)row * PROJ_ + I_ + ch;
        float acc = cb[ch] + pr[0] * cw[2 * CONV_ + ch];
        if (t >= 1) acc += pr[-(ptrdiff_t)PROJ_] * cw[CONV_ + ch];
        if (t >= 2) acc += pr[-2 * (ptrdiff_t)PROJ_] * cw[ch];
        o[c] = siluf(acc);
    } else if (c < 144) {
        const int h = c - 128;
        float v = proj[(size_t)row * PROJ_ + I_ + CONV_ + h] + dt_bias[h];
        o[c] = (v > 20.f) ? v : log1pf(__expf(v));
    }
}

// ======================= chunk-parallel SSM scan ============================
// Phase 1: per (half, b, h, chunk) CTA scan TC steps from s=0, emit y_local,
// store final local state + per-t cumulative dt (half 0 only). Unroll x4.
__global__ void __launch_bounds__(128) scan_p1(
    const float* __restrict__ proj, const float* __restrict__ cw,
    const float* __restrict__ cb, const float* __restrict__ A_log,
    const float* __restrict__ Dv, float* __restrict__ y)
{
    const int bi = blockIdx.x;
    const int half = bi >> 10;
    const int c = (bi >> 7) & 7;
    const int b = (bi >> 4) & 7;
    const int h = bi & 15;
    const int p = threadIdx.x;
    const int n_off = half * 32;
    const int t0 = c * TC;

    __shared__ float sB[4][32], sC[4][32], sDT[4];

    const float a = -__expf(A_log[h]);
    const float dcoef = (half == 0) ? Dv[h] : 0.f;

    const int xch = h * P_ + p;
    const float xw0 = cw[xch], xw1 = cw[CONV_ + xch], xw2 = cw[2 * CONV_ + xch];
    const float xbias = cb[xch];
    const int xcol = I_ + xch;

    const float* prow = proj + (size_t)b * T_ * PROJ_;
    const float* bcd = g_bcd + (size_t)(b * T_) * BCD_STR;
    float* cdout = g_cumdt + (b * H_ + h) * T_;

    float hx1 = 0.f, hx2 = 0.f;
    if (c > 0) {
        hx1 = prow[(size_t)(t0 - 1) * PROJ_ + xcol];
        hx2 = prow[(size_t)(t0 - 2) * PROJ_ + xcol];
    }

    float s[32];
    #pragma unroll
    for (int n = 0; n < 32; n++) s[n] = 0.f;
    float run = 0.f;

    float* yb = y + (size_t)half * BT * I_ + (size_t)b * T_ * I_ + h * P_ + p;

    for (int t = t0; t < t0 + TC; t += 4) {
        const float* r0 = prow + (size_t)t * PROJ_;
        const float* br = bcd + (size_t)t * BCD_STR;
        float xr[4];
        #pragma unroll
        for (int j = 0; j < 4; j++) xr[j] = r0[(size_t)j * PROJ_ + xcol];
        if (p < 32) {
            #pragma unroll
            for (int j = 0; j < 4; j++) sB[j][p] = br[j * BCD_STR + n_off + p];
        } else if (p < 64) {
            #pragma unroll
            for (int j = 0; j < 4; j++) sC[j][p - 32] = br[j * BCD_STR + 64 + n_off + (p - 32)];
        } else if (p < 68) {
            sDT[p - 64] = br[(p - 64) * BCD_STR + 128 + h];
        }
        float xs[4];
        xs[0] = siluf(xbias + xr[0] * xw2 + hx1 * xw1 + hx2 * xw0);
        xs[1] = siluf(xbias + xr[1] * xw2 + xr[0] * xw1 + hx1 * xw0);
        xs[2] = siluf(xbias + xr[2] * xw2 + xr[1] * xw1 + xr[0] * xw0);
        xs[3] = siluf(xbias + xr[3] * xw2 + xr[2] * xw1 + xr[1] * xw0);
        hx2 = xr[2]; hx1 = xr[3];
        __syncthreads();
        float dA[4], k[4];
        #pragma unroll
        for (int j = 0; j < 4; j++) {
            const float dtj = sDT[j];
            dA[j] = __expf(dtj * a);
            k[j] = dtj * xs[j];
        }
        if (half == 0 && p == 64) {
            #pragma unroll
            for (int j = 0; j < 4; j++) {
                run += sDT[j];
                cdout[t + j] = run;
            }
        }
        float ya[4], ybv[4];
        #pragma unroll
        for (int j = 0; j < 4; j++) { ya[j] = 0.f; ybv[j] = 0.f; }
        #pragma unroll
        for (int n = 0; n < 32; n += 2) {
            #pragma unroll
            for (int j = 0; j < 4; j++) {
                s[n]     = s[n]     * dA[j] + k[j] * sB[j][n];     ya[j]  += s[n]     * sC[j][n];
                s[n + 1] = s[n + 1] * dA[j] + k[j] * sB[j][n + 1]; ybv[j] += s[n + 1] * sC[j][n + 1];
            }
        }
        #pragma unroll
        for (int j = 0; j < 4; j++)
            yb[(size_t)(t + j) * I_] = ya[j] + ybv[j] + dcoef * xs[j];
        __syncthreads();
    }

    const size_t sbase = ((((size_t)half * B_ + b) * H_ + h) * CC + c) * CH_STRIDE;
    #pragma unroll
    for (int n = 0; n < 32; n++)
        g_state[sbase + n * 128 + p] = s[n];
}

// Phase 2: convert local final states -> true chunk-initial states (in place).
__global__ void __launch_bounds__(128) scan_p2(const float* __restrict__ A_log)
{
    const int bi = blockIdx.x;               // [0, 256)
    const int half = bi >> 7;
    const int b = (bi >> 4) & 7;
    const int h = bi & 15;
    const int p = threadIdx.x;
    const float a = -__expf(A_log[h]);

    float s[32];
    #pragma unroll
    for (int n = 0; n < 32; n++) s[n] = 0.f;

    const float* cd = g_cumdt + (b * H_ + h) * T_;
    const size_t base0 = (((size_t)half * B_ + b) * H_ + h) * CC * CH_STRIDE;
    for (int c = 0; c < CC; c++) {
        const float D = __expf(a * cd[c * TC + TC - 1]);
        const size_t sb = base0 + (size_t)c * CH_STRIDE;
        #pragma unroll
        for (int n = 0; n < 32; n++) {
            const size_t idx = sb + n * 128 + p;
            const float local = g_state[idx];
            g_state[idx] = s[n];
            s[n] = s[n] * D + local;
        }
    }
}

// Phase 3: correction, chunks 1..CC-1 only:
//   y_t += exp(a*cumdt_t) * (C_t . s_init).  Fully parallel over t.
__global__ void __launch_bounds__(128) scan_p3c(
    const float* __restrict__ A_log, float* __restrict__ y)
{
    const int bi = blockIdx.x;               // [0, 2*B*H*(CC-1))
    const int c = 1 + (bi % (CC - 1));
    const int r = bi / (CC - 1);
    const int half = r >> 7;
    const int b = (r >> 4) & 7;
    const int h = r & 15;
    const int p = threadIdx.x;
    const int n_off = half * 32;
    const int t0 = c * TC;

    __shared__ float sCx[4][32];
    __shared__ float sCD[4];

    const float a = -__expf(A_log[h]);

    float si[32];
    const size_t sbase = ((((size_t)half * B_ + b) * H_ + h) * CC + c) * CH_STRIDE;
    #pragma unroll
    for (int n = 0; n < 32; n++)
        si[n] = g_state[sbase + n * 128 + p];

    const float* bcdC = g_bcd + (size_t)(b * T_) * BCD_STR + 64 + n_off;
    const float* cd = g_cumdt + (b * H_ + h) * T_;
    float* yb = y + (size_t)half * BT * I_ + (size_t)b * T_ * I_ + h * P_ + p;

    const int lj = p >> 5;
    const int ln = p & 31;

    for (int t = t0; t < t0 + TC; t += 4) {
        sCx[lj][ln] = bcdC[(size_t)(t + lj) * BCD_STR + ln];
        if (p < 4) sCD[p] = cd[t + p];
        __syncthreads();
        #pragma unroll
        for (int j = 0; j < 4; j++) {
            const float prod = __expf(a * sCD[j]);
            float d0 = 0.f, d1 = 0.f;
            #pragma unroll
            for (int n = 0; n < 32; n += 2) {
                d0 += sCx[j][n] * si[n];
                d1 += sCx[j][n + 1] * si[n + 1];
            }
            const size_t yi = (size_t)(t + j) * I_;
            yb[yi] += prod * (d0 + d1);
        }
        __syncthreads();
    }
}

// ------- gated rmsnorm: warp per row, float4, no block barriers --------------
__global__ void __launch_bounds__(256) grms_kernel(
    float* __restrict__ yout, const float* __restrict__ y0p, const float* __restrict__ y1p,
    const float* __restrict__ proj, const float* __restrict__ w)
{
    const int lane = threadIdx.x & 31;
    const int row = blockIdx.x * 8 + (threadIdx.x >> 5);
    const float4* y0r = reinterpret_cast<const float4*>(y0p + (size_t)row * I_);
    const float4* y1r = reinterpret_cast<const float4*>(y1p + (size_t)row * I_);
    const float4* gr = reinterpret_cast<const float4*>(proj + (size_t)row * PROJ_);
    const float4* wr = reinterpret_cast<const float4*>(w);
    float4* orow = reinterpret_cast<float4*>(yout + (size_t)row * I_);
    float4 v[16];
    float ss = 0.f;
    #pragma unroll
    for (int k = 0; k < 16; k++) {
        const int i = lane + 32 * k;
        float4 a = y0r[i], b = y1r[i], g = gr[i];
        v[k].x = (a.x + b.x) * siluf(g.x);
        v[k].y = (a.y + b.y) * siluf(g.y);
        v[k].z = (a.z + b.z) * siluf(g.z);
        v[k].w = (a.w + b.w) * siluf(g.w);
        ss += v[k].x * v[k].x + v[k].y * v[k].y + v[k].z * v[k].z + v[k].w * v[k].w;
    }
    float tot = warp_reduce_sum(ss);
    float r = rsqrtf(tot * (1.f / (float)I_) + 1e-6f);
    #pragma unroll
    for (int k = 0; k < 16; k++) {
        const int i = lane + 32 * k;
        float4 wv = wr[i];
        float4 o;
        o.x = v[k].x * r * wv.x; o.y = v[k].y * r * wv.y;
        o.z = v[k].z * r * wv.z; o.w = v[k].w * r * wv.w;
        orow[i] = o;
    }
}

// ---------------- host launcher ----------------
extern "C" void kernel_launch(void* const* d_in, const int* in_sizes, int n_in,
                              void* d_out, int out_size)
{
    const float* x        = (const float*)d_in[0];
    const float* in_w     = (const float*)d_in[1];
    const float* in_b     = (const float*)d_in[2];
    const float* norm_w   = (const float*)d_in[3];
    const float* mix_in_w = (const float*)d_in[4];
    const float* conv_w   = (const float*)d_in[5];
    const float* conv_b   = (const float*)d_in[6];
    const float* dt_bias  = (const float*)d_in[7];
    const float* A_log    = (const float*)d_in[8];
    const float* Dvec     = (const float*)d_in[9];
    const float* gnorm_w  = (const float*)d_in[10];
    const float* mix_out_w= (const float*)d_in[11];
    const float* out_w    = (const float*)d_in[12];
    const float* out_b    = (const float*)d_in[13];
    const float* code_w   = (const float*)d_in[14];
    const float* code_b   = (const float*)d_in[15];
    float* out = (float*)d_out;

    float *h, *hn, *proj, *yb;
    cudaGetSymbolAddress((void**)&h,    g_h);
    cudaGetSymbolAddress((void**)&hn,   g_hn);
    cudaGetSymbolAddress((void**)&proj, g_proj);
    cudaGetSymbolAddress((void**)&yb,   g_y);
    float* yb0 = yb;
    float* yb1 = yb + (size_t)BT * I_;

    cudaFuncSetAttribute(gemm_tc, cudaFuncAttributeMaxDynamicSharedMemorySize, GEMM_SMEM);

    // h = x @ in_w + in_b
    gemm_tc<<<dim3(D_ / 128, BT / 128), 256, GEMM_SMEM>>>(x, in_w, h, BT, D_, IN_, in_b, 0);

    for (int l = 0; l < L_; l++) {
        rmsnorm_kernel<<<BT / 8, 256>>>(h, norm_w + l * D_, hn);
        gemm_tc<<<dim3((PROJ_ + 127) / 128, BT / 128), 256, GEMM_SMEM>>>(
            hn, mix_in_w + (size_t)l * D_ * PROJ_, proj, BT, PROJ_, D_, nullptr, 0);
        bcd_kernel<<<BT, 160>>>(
            proj, conv_w + (size_t)l * K_ * CONV_, conv_b + (size_t)l * CONV_,
            dt_bias + l * H_);
        scan_p1<<<2 * CC * B_ * H_, 128>>>(
            proj, conv_w + (size_t)l * K_ * CONV_, conv_b + (size_t)l * CONV_,
            A_log + l * H_, Dvec + l * H_, yb);
        scan_p2<<<2 * B_ * H_, 128>>>(A_log + l * H_);
        scan_p3c<<<2 * B_ * H_ * (CC - 1), 128>>>(A_log + l * H_, yb);
        grms_kernel<<<BT / 8, 256>>>(yb0, yb0, yb1, proj, gnorm_w + (size_t)l * I_);
        gemm_tc<<<dim3(D_ / 128, BT / 128), 256, GEMM_SMEM>>>(
            yb0, mix_out_w + (size_t)l * I_ * D_, h, BT, D_, I_, nullptr, 1);
    }

    // heads
    gemm_tc<<<dim3(OUT_ / 128, BT / 128), 256, GEMM_SMEM>>>(h, out_w, out, BT, OUT_, D_, out_b, 0);
    gemm_tc<<<dim3(CB_ / 128, BT / 128), 256, GEMM_SMEM>>>(
        h, code_w, out + (size_t)BT * OUT_, BT, CB_, D_, code_b, 0);
}